// round 13
// baseline (speedup 1.0000x reference)
#include <cuda_runtime.h>
#include <cstdint>

// ---------------- problem constants ----------------
#define S_LEN 2048
#define BATCH 4
#define HDIM  1024
#define MROWS (BATCH*S_LEN)        // 8192
#define SCALE_INV 0.03125f         // 1/sqrt(1024)
#define QMAX  16256.0f             // 127*128 (14-bit quant range)

// ---------------- fp32 scratch ----------------
__device__ float g_Q [(size_t)MROWS*HDIM];          // [B,S,H]
__device__ float g_K [(size_t)MROWS*HDIM];
__device__ float g_V [(size_t)MROWS*HDIM];
__device__ float g_Vt[(size_t)BATCH*HDIM*S_LEN];    // [B,H,S]
__device__ float g_P [(size_t)BATCH*S_LEN*S_LEN];   // scores (pre-softmax)

// ---------------- s8 limb planes + scales ----------------
__device__ int8_t q_x1 [(size_t)MROWS*HDIM], q_x0 [(size_t)MROWS*HDIM];
__device__ int8_t q_wq1[(size_t)HDIM*HDIM],  q_wq0[(size_t)HDIM*HDIM];
__device__ int8_t q_wk1[(size_t)HDIM*HDIM],  q_wk0[(size_t)HDIM*HDIM];
__device__ int8_t q_wv1[(size_t)HDIM*HDIM],  q_wv0[(size_t)HDIM*HDIM];
__device__ int8_t q_q1 [(size_t)MROWS*HDIM], q_q0 [(size_t)MROWS*HDIM];
__device__ int8_t q_k1 [(size_t)MROWS*HDIM], q_k0 [(size_t)MROWS*HDIM];
__device__ int8_t q_p1 [(size_t)MROWS*S_LEN], q_p0[(size_t)MROWS*S_LEN];
__device__ int8_t q_v1 [(size_t)BATCH*HDIM*S_LEN], q_v0[(size_t)BATCH*HDIM*S_LEN];
__device__ float s_x[MROWS], s_wq[HDIM], s_wk[HDIM], s_wv[HDIM];
__device__ float s_q[MROWS], s_k[MROWS], s_p[MROWS], s_vt[BATCH*HDIM];

// ---------------- helpers ----------------
__device__ __forceinline__ uint32_t smem_u32(const void* p) {
    uint32_t a;
    asm("{ .reg .u64 t; cvta.to.shared.u64 t, %1; cvt.u32.u64 %0, t; }" : "=r"(a) : "l"(p));
    return a;
}
__device__ __forceinline__ uint32_t lds32(uint32_t a) {
    uint32_t v; asm volatile("ld.shared.b32 %0, [%1];" : "=r"(v) : "r"(a)); return v;
}
#define CP16(dst, src) \
    asm volatile("cp.async.cg.shared.global [%0], [%1], 16;" :: "r"(dst), "l"(src) : "memory")
#define CP_COMMIT() asm volatile("cp.async.commit_group;" ::: "memory")
#define CP_WAIT1()  asm volatile("cp.async.wait_group 1;" ::: "memory")
#define CP_WAIT0()  asm volatile("cp.async.wait_group 0;" ::: "memory")

// m16n8k32 s8*s8 -> s32 accumulate (Ampere-compatible PTX, no 'a'-arch features)
#define MMA_S8(d, a, b) \
    asm volatile("mma.sync.aligned.m16n8k32.row.col.s32.s8.s8.s32 " \
        "{%0,%1,%2,%3}, {%4,%5,%6,%7}, {%8,%9}, {%0,%1,%2,%3};" \
        : "+r"((d)[0]), "+r"((d)[1]), "+r"((d)[2]), "+r"((d)[3]) \
        : "r"((a)[0]), "r"((a)[1]), "r"((a)[2]), "r"((a)[3]), \
          "r"((b)[0]), "r"((b)[1]))

// ---------------- smem layout ----------------
// Row stride 80 B (64 data + 16 pad): 8 consecutive rows -> banks 20r (distinct
// mod 32), same conflict-free pattern validated in R12.
// Stage: A1 | A0 | B1 | B0 planes, each 128 rows * 80 B.
#define ROWB 80
#define P_A1 0
#define P_A0 10240
#define P_B1 20480
#define P_B0 30720
#define STAGE 40960
#define SMEM_BYTES (2*STAGE)       // 81920

// ---------------- row quantization ----------------
// Per row: s = max|v|/QMAX ; q = rint(v/s) in +-16256 ; limbs q1 = rint(q/128)
// (+-127), q0 = q - 128*q1 (+-64ish).  E = elements per thread (K = 256*E).
template<int E, bool XORD>
__global__ void __launch_bounds__(256) rowquant(
    const float* __restrict__ src, int ld,
    int8_t* __restrict__ o1, int8_t* __restrict__ o0, float* __restrict__ scale)
{
    const int row = blockIdx.x;
    const int tid = threadIdx.x;
    const float* p;
    if (XORD) {            // x reorder: row r = b*S + s reads x[s, b, :]
        const int b = row >> 11, s = row & (S_LEN - 1);
        p = src + ((size_t)s * BATCH + b) * HDIM;
    } else {
        p = src + (size_t)row * ld;
    }

    float v[E]; float mx = 0.f;
#pragma unroll
    for (int i = 0; i < E; i++) { v[i] = p[tid + (i << 8)]; mx = fmaxf(mx, fabsf(v[i])); }
#pragma unroll
    for (int o = 16; o; o >>= 1) mx = fmaxf(mx, __shfl_xor_sync(0xffffffffu, mx, o));
    __shared__ float sred[8];
    if ((tid & 31) == 0) sred[tid >> 5] = mx;
    __syncthreads();
#pragma unroll
    for (int i = 0; i < 8; i++) mx = fmaxf(mx, sred[i]);

    const float inv = (mx > 1e-30f) ? (QMAX / mx) : 0.f;
    if (tid == 0) scale[row] = (mx > 1e-30f) ? (mx / QMAX) : 0.f;

    int8_t* d1 = o1 + (size_t)row * (256 * E);
    int8_t* d0 = o0 + (size_t)row * (256 * E);
#pragma unroll
    for (int i = 0; i < E; i++) {
        float qf = rintf(v[i] * inv);
        float h  = rintf(qf * 0.0078125f);          // /128
        d1[tid + (i << 8)] = (int8_t)(int)h;
        d0[tid + (i << 8)] = (int8_t)(int)(qf - 128.f * h);
    }
}

// ---------------- generic 128x128 s8 GEMM mainloop ----------------
// acc11 += A1.B1 ; accX += A1.B0 + A0.B1 over K. Warp layout 2(M) x 4(N),
// warp tile 64x32. k-tile = 64 s8 (two m16n8k32 steps). cp.async double buffer.
__device__ __forceinline__ void issue_tile(
    uint32_t sb_stage,
    const int8_t* A1, const int8_t* A0, size_t lda,
    const int8_t* B1, const int8_t* B0, size_t ldb, int kt)
{
    const int tid = threadIdx.x;
    const int r = tid >> 1, half = (tid & 1) * 32;
    const size_t ga = (size_t)r * lda + (size_t)kt * 64 + half;
    const size_t gb = (size_t)r * ldb + (size_t)kt * 64 + half;
    const uint32_t d = sb_stage + r * ROWB + half;
    CP16(d + P_A1,      A1 + ga); CP16(d + P_A1 + 16, A1 + ga + 16);
    CP16(d + P_A0,      A0 + ga); CP16(d + P_A0 + 16, A0 + ga + 16);
    CP16(d + P_B1,      B1 + gb); CP16(d + P_B1 + 16, B1 + gb + 16);
    CP16(d + P_B0,      B0 + gb); CP16(d + P_B0 + 16, B0 + gb + 16);
}

__device__ __forceinline__ void compute_tile(
    uint32_t sb_stage, int wm, int wn, int g, int tig,
    int32_t acc11[4][4][4], int32_t accX[4][4][4])
{
    const uint32_t rdA = sb_stage + (wm + g) * ROWB + tig * 4;
    const uint32_t rdB = sb_stage + (wn + g) * ROWB + tig * 4;
#pragma unroll
    for (int ks = 0; ks < 2; ks++) {
        const uint32_t co = ks * 32;                 // 32 s8 = 32 B per k32 step
        uint32_t a1[4][4], a0[4][4], b1[4][2], b0[4][2];
#pragma unroll
        for (int mt = 0; mt < 4; mt++) {
            const uint32_t ba = rdA + co + mt * (16 * ROWB);
            a1[mt][0] = lds32(ba + P_A1);
            a1[mt][1] = lds32(ba + P_A1 + 8 * ROWB);
            a1[mt][2] = lds32(ba + P_A1 + 16);
            a1[mt][3] = lds32(ba + P_A1 + 8 * ROWB + 16);
            a0[mt][0] = lds32(ba + P_A0);
            a0[mt][1] = lds32(ba + P_A0 + 8 * ROWB);
            a0[mt][2] = lds32(ba + P_A0 + 16);
            a0[mt][3] = lds32(ba + P_A0 + 8 * ROWB + 16);
        }
#pragma unroll
        for (int nt = 0; nt < 4; nt++) {
            const uint32_t bb = rdB + co + nt * (8 * ROWB);
            b1[nt][0] = lds32(bb + P_B1);
            b1[nt][1] = lds32(bb + P_B1 + 16);
            b0[nt][0] = lds32(bb + P_B0);
            b0[nt][1] = lds32(bb + P_B0 + 16);
        }
#pragma unroll
        for (int mt = 0; mt < 4; mt++)
#pragma unroll
            for (int nt = 0; nt < 4; nt++) {
                MMA_S8(acc11[mt][nt], a1[mt], b1[nt]);   // 16384 weight
                MMA_S8(accX[mt][nt],  a1[mt], b0[nt]);   // 128 weight
                MMA_S8(accX[mt][nt],  a0[mt], b1[nt]);   // 128 weight
            }
    }
}

__device__ __forceinline__ void gemm_s8(
    const int8_t* A1, const int8_t* A0, size_t lda,
    const int8_t* B1, const int8_t* B0, size_t ldb,
    int K, char* smem, int32_t acc11[4][4][4], int32_t accX[4][4][4])
{
    const int tid = threadIdx.x, wid = tid >> 5, lane = tid & 31;
    const int wm = (wid >> 2) * 64, wn = (wid & 3) * 32;
    const int g = lane >> 2, tig = lane & 3;
    const uint32_t sb = smem_u32(smem);
    const int T = K >> 6;

    issue_tile(sb, A1, A0, lda, B1, B0, ldb, 0);
    CP_COMMIT();
    for (int t = 0; t < T; t++) {
        if (t + 1 < T) {
            issue_tile(sb + (uint32_t)((t + 1) & 1) * STAGE, A1, A0, lda, B1, B0, ldb, t + 1);
            CP_COMMIT();
            CP_WAIT1();
        } else {
            CP_WAIT0();
        }
        __syncthreads();
        compute_tile(sb + (uint32_t)(t & 1) * STAGE, wm, wn, g, tig, acc11, accX);
        __syncthreads();
    }
}

#define ACC_INIT(acc11, accX) do {                        \
    _Pragma("unroll") for (int i = 0; i < 4; i++)         \
    _Pragma("unroll") for (int j = 0; j < 4; j++)         \
    _Pragma("unroll") for (int r = 0; r < 4; r++)         \
        { acc11[i][j][r] = 0; accX[i][j][r] = 0; }        \
} while (0)

// combine limbs: value = sA*sB*(16384*S11 + 128*Sx)
__device__ __forceinline__ float combine(int32_t s11, int32_t sx, float ss) {
    return (16384.f * (float)s11 + 128.f * (float)sx) * ss;
}

// =====================================================================
// Kernel: QKV projection. grid (8, 64), 256 thr. Writes fp32 [B,S,H].
// =====================================================================
__global__ void __launch_bounds__(256, 1) proj_s8(
    const int8_t* __restrict__ W1, const int8_t* __restrict__ W0,
    const float* __restrict__ sw, const float* __restrict__ bias,
    float* __restrict__ outp)
{
    extern __shared__ char smem[];
    const int m0 = blockIdx.y * 128;
    const int n0 = blockIdx.x * 128;

    int32_t acc11[4][4][4], accX[4][4][4];
    ACC_INIT(acc11, accX);

    gemm_s8(q_x1 + (size_t)m0 * HDIM, q_x0 + (size_t)m0 * HDIM, HDIM,
            W1 + (size_t)n0 * HDIM,  W0 + (size_t)n0 * HDIM,  HDIM,
            HDIM, smem, acc11, accX);

    const int tid = threadIdx.x, wid = tid >> 5, lane = tid & 31;
    const int wm = (wid >> 2) * 64, wn = (wid & 3) * 32;
    const int g = lane >> 2, tig = lane & 3;
#pragma unroll
    for (int mt = 0; mt < 4; mt++)
#pragma unroll
        for (int nt = 0; nt < 4; nt++) {
            const int row = m0 + wm + mt * 16 + g;
            const int col = n0 + wn + nt * 8 + tig * 2;
            const float sA0 = s_x[row], sA1 = s_x[row + 8];
            const float sB0 = sw[col],  sB1 = sw[col + 1];
            const float2 bv = *(const float2*)(bias + col);
            float2 o0 = make_float2(combine(acc11[mt][nt][0], accX[mt][nt][0], sA0 * sB0) + bv.x,
                                    combine(acc11[mt][nt][1], accX[mt][nt][1], sA0 * sB1) + bv.y);
            float2 o1 = make_float2(combine(acc11[mt][nt][2], accX[mt][nt][2], sA1 * sB0) + bv.x,
                                    combine(acc11[mt][nt][3], accX[mt][nt][3], sA1 * sB1) + bv.y);
            *(float2*)(outp + (size_t)row * HDIM + col)       = o0;
            *(float2*)(outp + (size_t)(row + 8) * HDIM + col) = o1;
        }
}

// =====================================================================
// Kernel: V transpose (fp32), unchanged from R12.
// =====================================================================
__global__ void __launch_bounds__(256) transpose_v()
{
    __shared__ float tile[32][33];
    const int b  = blockIdx.z;
    const int s0 = blockIdx.x * 32;
    const int h0 = blockIdx.y * 32;
    const int tx = threadIdx.x, ty = threadIdx.y;
    const float* src = g_V + ((size_t)b * S_LEN + s0) * HDIM + h0;
#pragma unroll
    for (int i = 0; i < 32; i += 8)
        tile[ty + i][tx] = src[(size_t)(ty + i) * HDIM + tx];
    __syncthreads();
    float* dst = g_Vt + ((size_t)b * HDIM + h0) * S_LEN + s0;
#pragma unroll
    for (int i = 0; i < 32; i += 8)
        dst[(size_t)(ty + i) * S_LEN + tx] = tile[tx][ty + i];
}

// =====================================================================
// Kernel: scores -> g_P fp32.  grid (16, 16, 4)
// =====================================================================
__global__ void __launch_bounds__(256, 1) scores_s8(
    const float* __restrict__ ssm, const float* __restrict__ beta_p)
{
    extern __shared__ char smem[];
    const int q0  = blockIdx.y * 128;
    const int kk0 = blockIdx.x * 128;
    const int b   = blockIdx.z;
    const size_t arow = (size_t)(b * S_LEN + q0);
    const size_t brow = (size_t)(b * S_LEN + kk0);

    int32_t acc11[4][4][4], accX[4][4][4];
    ACC_INIT(acc11, accX);

    gemm_s8(q_q1 + arow * HDIM, q_q0 + arow * HDIM, HDIM,
            q_k1 + brow * HDIM, q_k0 + brow * HDIM, HDIM,
            HDIM, smem, acc11, accX);

    const float beta = __ldg(beta_p);
    const int tid = threadIdx.x, wid = tid >> 5, lane = tid & 31;
    const int wm = (wid >> 2) * 64, wn = (wid & 3) * 32;
    const int g = lane >> 2, tig = lane & 3;
    float*       Pb = g_P + (size_t)b * S_LEN * S_LEN;
    const float* Sb = ssm + (size_t)b * S_LEN * S_LEN;
#pragma unroll
    for (int mt = 0; mt < 4; mt++)
#pragma unroll
        for (int nt = 0; nt < 4; nt++) {
            const int row = q0 + wm + mt * 16 + g;
            const int col = kk0 + wn + nt * 8 + tig * 2;
            const float sA0 = s_q[b * S_LEN + row] * SCALE_INV;
            const float sA1 = s_q[b * S_LEN + row + 8] * SCALE_INV;
            const float sB0 = s_k[b * S_LEN + col], sB1 = s_k[b * S_LEN + col + 1];
            const float2 v0 = *(const float2*)(Sb + (size_t)row * S_LEN + col);
            const float2 v1 = *(const float2*)(Sb + (size_t)(row + 8) * S_LEN + col);
            float2 o0 = make_float2(combine(acc11[mt][nt][0], accX[mt][nt][0], sA0 * sB0) + beta * v0.x,
                                    combine(acc11[mt][nt][1], accX[mt][nt][1], sA0 * sB1) + beta * v0.y);
            float2 o1 = make_float2(combine(acc11[mt][nt][2], accX[mt][nt][2], sA1 * sB0) + beta * v1.x,
                                    combine(acc11[mt][nt][3], accX[mt][nt][3], sA1 * sB1) + beta * v1.y);
            *(float2*)(Pb + (size_t)row * S_LEN + col)       = o0;
            *(float2*)(Pb + (size_t)(row + 8) * S_LEN + col) = o1;
        }
}

// =====================================================================
// Kernel: softmax + fused quantization of P into s8 limbs.
// Row max of P is 1/sum (exp(max-max)=1), so q = rint(v * QMAX) directly.
// =====================================================================
__global__ void __launch_bounds__(256) softmax_quant()
{
    const int row = blockIdx.x;                    // 0 .. B*S-1
    const float* p = g_P + (size_t)row * S_LEN;
    const int tid = threadIdx.x;

    float v[8];
    float mx = -1e30f;
#pragma unroll
    for (int i = 0; i < 8; i++) { v[i] = p[tid + (i << 8)]; mx = fmaxf(mx, v[i]); }
#pragma unroll
    for (int o = 16; o; o >>= 1) mx = fmaxf(mx, __shfl_xor_sync(0xffffffffu, mx, o));
    __shared__ float sred[8];
    if ((tid & 31) == 0) sred[tid >> 5] = mx;
    __syncthreads();
#pragma unroll
    for (int i = 0; i < 8; i++) mx = fmaxf(mx, sred[i]);

    float sum = 0.f;
#pragma unroll
    for (int i = 0; i < 8; i++) { v[i] = __expf(v[i] - mx); sum += v[i]; }
#pragma unroll
    for (int o = 16; o; o >>= 1) sum += __shfl_xor_sync(0xffffffffu, sum, o);
    __syncthreads();
    if ((tid & 31) == 0) sred[tid >> 5] = sum;
    __syncthreads();
    sum = 0.f;
#pragma unroll
    for (int i = 0; i < 8; i++) sum += sred[i];

    const float inv = 1.0f / sum;                  // = row max of P
    if (tid == 0) s_p[row] = inv / QMAX;
    int8_t* d1 = q_p1 + (size_t)row * S_LEN;
    int8_t* d0 = q_p0 + (size_t)row * S_LEN;
#pragma unroll
    for (int i = 0; i < 8; i++) {
        float qf = rintf(v[i] * QMAX);             // P/s = (v*inv)*QMAX/inv
        float h  = rintf(qf * 0.0078125f);
        d1[tid + (i << 8)] = (int8_t)(int)h;
        d0[tid + (i << 8)] = (int8_t)(int)(qf - 128.f * h);
    }
}

// =====================================================================
// Kernel: out[s,b,h] = sum_k P[b,s,k] * Vt[b,h,k].  grid (8, 16, 4)
// =====================================================================
__global__ void __launch_bounds__(256, 1) out_s8(float* __restrict__ out)
{
    extern __shared__ char smem[];
    const int q0 = blockIdx.y * 128;
    const int h0 = blockIdx.x * 128;
    const int b  = blockIdx.z;
    const size_t arow = (size_t)(b * S_LEN + q0);
    const size_t brow = (size_t)(b * HDIM + h0);

    int32_t acc11[4][4][4], accX[4][4][4];
    ACC_INIT(acc11, accX);

    gemm_s8(q_p1 + arow * S_LEN, q_p0 + arow * S_LEN, S_LEN,
            q_v1 + brow * S_LEN, q_v0 + brow * S_LEN, S_LEN,
            S_LEN, smem, acc11, accX);

    const int tid = threadIdx.x, wid = tid >> 5, lane = tid & 31;
    const int wm = (wid >> 2) * 64, wn = (wid & 3) * 32;
    const int g = lane >> 2, tig = lane & 3;
#pragma unroll
    for (int mt = 0; mt < 4; mt++)
#pragma unroll
        for (int nt = 0; nt < 4; nt++) {
            const int row = q0 + wm + mt * 16 + g;       // s
            const int col = h0 + wn + nt * 8 + tig * 2;  // h
            const float sA0 = s_p[b * S_LEN + row], sA1 = s_p[b * S_LEN + row + 8];
            const float sB0 = s_vt[b * HDIM + col], sB1 = s_vt[b * HDIM + col + 1];
            float* d0 = out + (size_t)row * (BATCH * HDIM) + (size_t)b * HDIM + col;
            float* d1 = out + (size_t)(row + 8) * (BATCH * HDIM) + (size_t)b * HDIM + col;
            *(float2*)d0 = make_float2(combine(acc11[mt][nt][0], accX[mt][nt][0], sA0 * sB0),
                                       combine(acc11[mt][nt][1], accX[mt][nt][1], sA0 * sB1));
            *(float2*)d1 = make_float2(combine(acc11[mt][nt][2], accX[mt][nt][2], sA1 * sB0),
                                       combine(acc11[mt][nt][3], accX[mt][nt][3], sA1 * sB1));
        }
}

// =====================================================================
extern "C" void kernel_launch(void* const* d_in, const int* in_sizes, int n_in,
                              void* d_out, int out_size)
{
    const float* x    = (const float*)d_in[0];
    const float* ssm  = (const float*)d_in[1];
    const float* Wq   = (const float*)d_in[2];
    const float* bq   = (const float*)d_in[3];
    const float* Wk   = (const float*)d_in[4];
    const float* bk   = (const float*)d_in[5];
    const float* Wv   = (const float*)d_in[6];
    const float* bv   = (const float*)d_in[7];
    const float* beta = (const float*)d_in[8];
    float* out = (float*)d_out;

    cudaFuncSetAttribute(proj_s8,   cudaFuncAttributeMaxDynamicSharedMemorySize, SMEM_BYTES);
    cudaFuncSetAttribute(scores_s8, cudaFuncAttributeMaxDynamicSharedMemorySize, SMEM_BYTES);
    cudaFuncSetAttribute(out_s8,    cudaFuncAttributeMaxDynamicSharedMemorySize, SMEM_BYTES);

    // device-global symbol addresses (host side)
    float *dQ, *dK, *dV, *dVt;
    int8_t *dwq1, *dwq0, *dwk1, *dwk0, *dwv1, *dwv0, *dq1, *dq0, *dk1, *dk0, *dv1, *dv0;
    float *dswq, *dswk, *dswv, *dsq, *dsk, *dsvt;
    cudaGetSymbolAddress((void**)&dQ,  g_Q);  cudaGetSymbolAddress((void**)&dK,  g_K);
    cudaGetSymbolAddress((void**)&dV,  g_V);  cudaGetSymbolAddress((void**)&dVt, g_Vt);
    cudaGetSymbolAddress((void**)&dwq1, q_wq1); cudaGetSymbolAddress((void**)&dwq0, q_wq0);
    cudaGetSymbolAddress((void**)&dwk1, q_wk1); cudaGetSymbolAddress((void**)&dwk0, q_wk0);
    cudaGetSymbolAddress((void**)&dwv1, q_wv1); cudaGetSymbolAddress((void**)&dwv0, q_wv0);
    cudaGetSymbolAddress((void**)&dq1, q_q1);   cudaGetSymbolAddress((void**)&dq0, q_q0);
    cudaGetSymbolAddress((void**)&dk1, q_k1);   cudaGetSymbolAddress((void**)&dk0, q_k0);
    cudaGetSymbolAddress((void**)&dv1, q_v1);   cudaGetSymbolAddress((void**)&dv0, q_v0);
    cudaGetSymbolAddress((void**)&dswq, s_wq);  cudaGetSymbolAddress((void**)&dswk, s_wk);
    cudaGetSymbolAddress((void**)&dswv, s_wv);
    cudaGetSymbolAddress((void**)&dsq, s_q);    cudaGetSymbolAddress((void**)&dsk, s_k);
    cudaGetSymbolAddress((void**)&dsvt, s_vt);
    int8_t *dx1, *dx0; float* dsx;
    cudaGetSymbolAddress((void**)&dx1, q_x1);   cudaGetSymbolAddress((void**)&dx0, q_x0);
    cudaGetSymbolAddress((void**)&dsx, s_x);

    dim3 blk(256);

    // 1. quantize inputs
    rowquant<4, true ><<<MROWS, blk>>>(x, HDIM, dx1, dx0, dsx);
    rowquant<4, false><<<HDIM,  blk>>>(Wq, HDIM, dwq1, dwq0, dswq);
    rowquant<4, false><<<HDIM,  blk>>>(Wk, HDIM, dwk1, dwk0, dswk);
    rowquant<4, false><<<HDIM,  blk>>>(Wv, HDIM, dwv1, dwv0, dswv);

    // 2. projections (fp32 results)
    dim3 gproj(HDIM / 128, MROWS / 128);
    proj_s8<<<gproj, blk, SMEM_BYTES>>>(dwq1, dwq0, dswq, bq, dQ);
    proj_s8<<<gproj, blk, SMEM_BYTES>>>(dwk1, dwk0, dswk, bk, dK);
    proj_s8<<<gproj, blk, SMEM_BYTES>>>(dwv1, dwv0, dswv, bv, dV);

    // 3. quantize Q, K; transpose + quantize V
    rowquant<4, false><<<MROWS, blk>>>(dQ, HDIM, dq1, dq0, dsq);
    rowquant<4, false><<<MROWS, blk>>>(dK, HDIM, dk1, dk0, dsk);
    transpose_v<<<dim3(S_LEN / 32, HDIM / 32, BATCH), dim3(32, 8)>>>();
    rowquant<8, false><<<BATCH * HDIM, blk>>>(dVt, S_LEN, dv1, dv0, dsvt);

    // 4. scores -> softmax(+quant) -> out
    scores_s8<<<dim3(S_LEN / 128, S_LEN / 128, BATCH), blk, SMEM_BYTES>>>(ssm, beta);
    softmax_quant<<<MROWS, blk>>>();
    out_s8<<<dim3(HDIM / 128, S_LEN / 128, BATCH), blk, SMEM_BYTES>>>(out);
}

// round 14
// speedup vs baseline: 2.3958x; 2.3958x over previous
#include <cuda_runtime.h>
#include <cuda_fp16.h>
#include <cstdint>

// ---------------- problem constants ----------------
#define S_LEN 2048
#define BATCH 4
#define HDIM  1024
#define MROWS (BATCH*S_LEN)        // 8192
#define SCALE_INV 0.03125f         // 1/sqrt(1024)

// ---------------- scratch (device globals; allocation-guard-safe) ----------
__device__ float g_Q [(size_t)MROWS*HDIM];          // [B,S,H]
__device__ float g_K [(size_t)MROWS*HDIM];
__device__ float g_V [(size_t)MROWS*HDIM];
__device__ float g_Vt[(size_t)BATCH*HDIM*S_LEN];    // [B,H,S]
__device__ float g_P [(size_t)BATCH*S_LEN*S_LEN];   // [B,S,S]

// ---------------- smem layout ----------------
// Row stride 80 B (64 B data as fp16 = 32 elems + 16 pad): 8 consecutive rows
// hit distinct banks (validated in R12). Planes per stage: A_hi | A_lo | B_hi.
#define ROWB 80
#define P_AH 0
#define P_AL 10240
#define P_BH 20480
#define STAGE 30720
#define SMEM_BYTES (2*STAGE)       // 61440

// ---------------- helpers ----------------
__device__ __forceinline__ uint32_t smem_u32(const void* p) {
    uint32_t a;
    asm("{ .reg .u64 t; cvta.to.shared.u64 t, %1; cvt.u32.u64 %0, t; }" : "=r"(a) : "l"(p));
    return a;
}
__device__ __forceinline__ uint32_t lds32(uint32_t a) {
    uint32_t v; asm volatile("ld.shared.b32 %0, [%1];" : "=r"(v) : "r"(a)); return v;
}
#define STS128(r0, r1, r2, r3, addr) \
    asm volatile("st.shared.v4.b32 [%0], {%1, %2, %3, %4};" \
        :: "r"(addr), "r"(r0), "r"(r1), "r"(r2), "r"(r3) : "memory")

// fp16 split: hi = rn(x) (11-bit), lo = rn(x - hi). x0 -> low half of packed b32.
__device__ __forceinline__ void split2(float x0, float x1, uint32_t& hi, uint32_t& lo) {
    __half2 h = __floats2half2_rn(x0, x1);
    float2 hf = __half22float2(h);
    __half2 l = __floats2half2_rn(x0 - hf.x, x1 - hf.y);
    hi = *(uint32_t*)&h;
    lo = *(uint32_t*)&l;
}
__device__ __forceinline__ uint32_t cvt2(float x0, float x1) {
    __half2 h = __floats2half2_rn(x0, x1);
    return *(uint32_t*)&h;
}

// m16n8k16 row.col fp16 -> f32 accumulate (Ampere-compatible PTX)
#define MMA_F16(d, a, b) \
    asm volatile("mma.sync.aligned.m16n8k16.row.col.f32.f16.f16.f32 " \
        "{%0,%1,%2,%3}, {%4,%5,%6,%7}, {%8,%9}, {%0,%1,%2,%3};" \
        : "+f"((d)[0]), "+f"((d)[1]), "+f"((d)[2]), "+f"((d)[3]) \
        : "r"((a)[0]), "r"((a)[1]), "r"((a)[2]), "r"((a)[3]), \
          "r"((b)[0]), "r"((b)[1]))

// Split one tile-row chunk (16 floats) of A (hi+lo) and B (hi only) into smem.
__device__ __forceinline__ void store_split(uint32_t stA, uint32_t stB,
                                            const float4* ra, const float4* rb)
{
    uint32_t h[8], l[8];
#pragma unroll
    for (int j = 0; j < 4; j++) {
        split2(ra[j].x, ra[j].y, h[2*j],   l[2*j]);
        split2(ra[j].z, ra[j].w, h[2*j+1], l[2*j+1]);
    }
    STS128(h[0], h[1], h[2], h[3], stA);
    STS128(h[4], h[5], h[6], h[7], stA + 16);
    STS128(l[0], l[1], l[2], l[3], stA + (P_AL - P_AH));
    STS128(l[4], l[5], l[6], l[7], stA + (P_AL - P_AH) + 16);
    uint32_t hb[8];
#pragma unroll
    for (int j = 0; j < 4; j++) {
        hb[2*j]   = cvt2(rb[j].x, rb[j].y);
        hb[2*j+1] = cvt2(rb[j].z, rb[j].w);
    }
    STS128(hb[0], hb[1], hb[2], hb[3], stB);
    STS128(hb[4], hb[5], hb[6], hb[7], stB + 16);
}

// ---------------- generic 128x128 GEMM mainloop (2xFP16 emulated fp32) ------
// acc += (A_hi + A_lo) . B_hi.  Warp layout 2(M) x 4(N), warp tile 64x32,
// double-buffered 128x128x32 stages, register-prefetch loader (R12-proven).
__device__ __forceinline__ void gemm_main(const float* __restrict__ A, int lda,
                                          const float* __restrict__ B, int ldb,
                                          int K, char* smem, float acc[4][4][4])
{
    const int tid  = threadIdx.x;
    const int wid  = tid >> 5, lane = tid & 31;
    const int wm   = (wid >> 2) * 64;
    const int wn   = (wid & 3) * 32;
    const int g    = lane >> 2, tig = lane & 3;
    const uint32_t sb = smem_u32(smem);

    // loader: 2 threads per row, 16 floats each
    const int lrow = tid >> 1;
    const int k0   = (tid & 1) * 16;
    const float* aP = A + (size_t)lrow * lda + k0;
    const float* bP = B + (size_t)lrow * ldb + k0;
    const uint32_t stA = sb + P_AH + lrow * ROWB + (tid & 1) * 32;
    const uint32_t stB = sb + P_BH + lrow * ROWB + (tid & 1) * 32;

    const uint32_t rdA = sb + P_AH + (wm + g) * ROWB + tig * 4;
    const uint32_t rdB = sb + P_BH + (wn + g) * ROWB + tig * 4;

    float4 ra[4], rb[4];
#pragma unroll
    for (int j = 0; j < 4; j++) {
        ra[j] = *(const float4*)(aP + j * 4);
        rb[j] = *(const float4*)(bP + j * 4);
    }
    store_split(stA, stB, ra, rb);
    __syncthreads();

    const int T = K >> 5;                     // 32-wide K tiles
    for (int t = 0; t < T; ++t) {
        const uint32_t so = (uint32_t)(t & 1) * STAGE;

        if (t + 1 < T) {                      // prefetch next tile into regs
            const int kk = (t + 1) << 5;
#pragma unroll
            for (int j = 0; j < 4; j++) {
                ra[j] = *(const float4*)(aP + kk + j * 4);
                rb[j] = *(const float4*)(bP + kk + j * 4);
            }
        }

#pragma unroll
        for (int ks = 0; ks < 2; ks++) {      // two k16 steps per tile
            const uint32_t co = so + ks * 32; // 16 fp16 = 32 B
            uint32_t ah[4][4], al[4][4], bh[4][2];
#pragma unroll
            for (int mt = 0; mt < 4; mt++) {
                uint32_t ba = rdA + co + mt * (16 * ROWB);
                ah[mt][0] = lds32(ba);
                ah[mt][1] = lds32(ba + 8 * ROWB);
                ah[mt][2] = lds32(ba + 16);
                ah[mt][3] = lds32(ba + 8 * ROWB + 16);
                ba += (P_AL - P_AH);
                al[mt][0] = lds32(ba);
                al[mt][1] = lds32(ba + 8 * ROWB);
                al[mt][2] = lds32(ba + 16);
                al[mt][3] = lds32(ba + 8 * ROWB + 16);
            }
#pragma unroll
            for (int nt = 0; nt < 4; nt++) {
                uint32_t bb = rdB + co + nt * (8 * ROWB);
                bh[nt][0] = lds32(bb);
                bh[nt][1] = lds32(bb + 16);
            }
#pragma unroll
            for (int mt = 0; mt < 4; mt++)
#pragma unroll
                for (int nt = 0; nt < 4; nt++) {
                    MMA_F16(acc[mt][nt], ah[mt], bh[nt]);   // hi pass
                    MMA_F16(acc[mt][nt], al[mt], bh[nt]);   // lo pass
                }
        }

        if (t + 1 < T)
            store_split(stA + ((uint32_t)((t + 1) & 1) * STAGE),
                        stB + ((uint32_t)((t + 1) & 1) * STAGE), ra, rb);
        __syncthreads();
    }
}

// Output coords for acc[mt][nt]:
//   row = m0 + wm + mt*16 + g (+8 for regs 2,3); col = n0 + wn + nt*8 + tig*2

// =====================================================================
// Kernel 1: fused QKV projection. z selects {Wq,bq,g_Q} / {Wk,..} / {Wv,..}.
// out[r,o] = sum_h x[s,b,h]*W[o,h] + b[o], r = b*S+s. grid (8, 64, 3).
// =====================================================================
__global__ void __launch_bounds__(256, 1) proj_mma(
    const float* __restrict__ x,
    const float* __restrict__ Wq, const float* __restrict__ Wk,
    const float* __restrict__ Wv,
    const float* __restrict__ bq, const float* __restrict__ bk,
    const float* __restrict__ bv)
{
    extern __shared__ char smem[];
    const int m0 = blockIdx.y * 128;
    const int n0 = blockIdx.x * 128;
    const int z  = blockIdx.z;
    const float* W    = (z == 0) ? Wq : (z == 1) ? Wk : Wv;
    const float* bias = (z == 0) ? bq : (z == 1) ? bk : bv;
    float* outp       = (z == 0) ? g_Q : (z == 1) ? g_K : g_V;

    const int bb = m0 >> 11;
    const int s0 = m0 & (S_LEN - 1);
    const float* Abase = x + ((size_t)s0 * BATCH + bb) * HDIM;  // row stride B*H
    const float* Bbase = W + (size_t)n0 * HDIM;

    float acc[4][4][4];
#pragma unroll
    for (int i = 0; i < 4; i++)
#pragma unroll
        for (int j = 0; j < 4; j++)
#pragma unroll
            for (int r = 0; r < 4; r++) acc[i][j][r] = 0.f;

    gemm_main(Abase, BATCH * HDIM, Bbase, HDIM, HDIM, smem, acc);

    const int tid = threadIdx.x, wid = tid >> 5, lane = tid & 31;
    const int wm = (wid >> 2) * 64, wn = (wid & 3) * 32;
    const int g = lane >> 2, tig = lane & 3;
#pragma unroll
    for (int mt = 0; mt < 4; mt++)
#pragma unroll
        for (int nt = 0; nt < 4; nt++) {
            const int row = m0 + wm + mt * 16 + g;
            const int col = n0 + wn + nt * 8 + tig * 2;
            const float2 bv2 = *(const float2*)(bias + col);
            float2 o0 = make_float2(acc[mt][nt][0] + bv2.x, acc[mt][nt][1] + bv2.y);
            float2 o1 = make_float2(acc[mt][nt][2] + bv2.x, acc[mt][nt][3] + bv2.y);
            *(float2*)(outp + (size_t)row * HDIM + col)       = o0;
            *(float2*)(outp + (size_t)(row + 8) * HDIM + col) = o1;
        }
}

// =====================================================================
// Kernel 2: V transpose  g_Vt[b][h][s] = g_V[b][s][h]
// =====================================================================
__global__ void __launch_bounds__(256) transpose_v()
{
    __shared__ float tile[32][33];
    const int b  = blockIdx.z;
    const int s0 = blockIdx.x * 32;
    const int h0 = blockIdx.y * 32;
    const int tx = threadIdx.x, ty = threadIdx.y;
    const float* src = g_V + ((size_t)b * S_LEN + s0) * HDIM + h0;
#pragma unroll
    for (int i = 0; i < 32; i += 8)
        tile[ty + i][tx] = src[(size_t)(ty + i) * HDIM + tx];
    __syncthreads();
    float* dst = g_Vt + ((size_t)b * HDIM + h0) * S_LEN + s0;
#pragma unroll
    for (int i = 0; i < 32; i += 8)
        dst[(size_t)(ty + i) * S_LEN + tx] = tile[tx][ty + i];
}

// =====================================================================
// Kernel 3: scores  P[b,q,k] = (Q[b,q,:].K[b,k,:])/32 + beta*ssm[b,q,k]
// grid (16, 16, 4)
// =====================================================================
__global__ void __launch_bounds__(256, 1) scores_mma(
    const float* __restrict__ ssm, const float* __restrict__ beta_p)
{
    extern __shared__ char smem[];
    const int q0  = blockIdx.y * 128;
    const int kk0 = blockIdx.x * 128;
    const int b   = blockIdx.z;
    const float* Abase = g_Q + (size_t)(b * S_LEN + q0) * HDIM;
    const float* Bbase = g_K + (size_t)(b * S_LEN + kk0) * HDIM;

    float acc[4][4][4];
#pragma unroll
    for (int i = 0; i < 4; i++)
#pragma unroll
        for (int j = 0; j < 4; j++)
#pragma unroll
            for (int r = 0; r < 4; r++) acc[i][j][r] = 0.f;

    gemm_main(Abase, HDIM, Bbase, HDIM, HDIM, smem, acc);

    const float beta = __ldg(beta_p);
    const int tid = threadIdx.x, wid = tid >> 5, lane = tid & 31;
    const int wm = (wid >> 2) * 64, wn = (wid & 3) * 32;
    const int g = lane >> 2, tig = lane & 3;
    float*       Pb = g_P + (size_t)b * S_LEN * S_LEN;
    const float* Sb = ssm + (size_t)b * S_LEN * S_LEN;
#pragma unroll
    for (int mt = 0; mt < 4; mt++)
#pragma unroll
        for (int nt = 0; nt < 4; nt++) {
            const int row = q0 + wm + mt * 16 + g;
            const int col = kk0 + wn + nt * 8 + tig * 2;
            const float2 s0 = *(const float2*)(Sb + (size_t)row * S_LEN + col);
            const float2 s1 = *(const float2*)(Sb + (size_t)(row + 8) * S_LEN + col);
            float2 o0 = make_float2(acc[mt][nt][0] * SCALE_INV + beta * s0.x,
                                    acc[mt][nt][1] * SCALE_INV + beta * s0.y);
            float2 o1 = make_float2(acc[mt][nt][2] * SCALE_INV + beta * s1.x,
                                    acc[mt][nt][3] * SCALE_INV + beta * s1.y);
            *(float2*)(Pb + (size_t)row * S_LEN + col)       = o0;
            *(float2*)(Pb + (size_t)(row + 8) * S_LEN + col) = o1;
        }
}

// =====================================================================
// Kernel 4: row-wise stable softmax over g_P, in place (proven)
// =====================================================================
__global__ void __launch_bounds__(256) softmax_kernel()
{
    const int row = blockIdx.x;
    float* p = g_P + (size_t)row * S_LEN;
    const int tid = threadIdx.x;

    float v[8];
    float mx = -1e30f;
#pragma unroll
    for (int i = 0; i < 8; i++) { v[i] = p[tid + (i << 8)]; mx = fmaxf(mx, v[i]); }
#pragma unroll
    for (int o = 16; o; o >>= 1) mx = fmaxf(mx, __shfl_xor_sync(0xffffffffu, mx, o));
    __shared__ float sred[8];
    if ((tid & 31) == 0) sred[tid >> 5] = mx;
    __syncthreads();
#pragma unroll
    for (int i = 0; i < 8; i++) mx = fmaxf(mx, sred[i]);

    float sum = 0.f;
#pragma unroll
    for (int i = 0; i < 8; i++) { v[i] = __expf(v[i] - mx); sum += v[i]; }
#pragma unroll
    for (int o = 16; o; o >>= 1) sum += __shfl_xor_sync(0xffffffffu, sum, o);
    __syncthreads();
    if ((tid & 31) == 0) sred[tid >> 5] = sum;
    __syncthreads();
    sum = 0.f;
#pragma unroll
    for (int i = 0; i < 8; i++) sum += sred[i];

    const float inv = 1.0f / sum;
#pragma unroll
    for (int i = 0; i < 8; i++) p[tid + (i << 8)] = v[i] * inv;
}

// =====================================================================
// Kernel 5: out[s,b,h] = sum_k P[b,s,k] * Vt[b,h,k].  grid (8, 16, 4)
// =====================================================================
__global__ void __launch_bounds__(256, 1) out_mma(float* __restrict__ out)
{
    extern __shared__ char smem[];
    const int q0 = blockIdx.y * 128;
    const int h0 = blockIdx.x * 128;
    const int b  = blockIdx.z;
    const float* Abase = g_P  + (size_t)b * S_LEN * S_LEN + (size_t)q0 * S_LEN;
    const float* Bbase = g_Vt + (size_t)b * HDIM * S_LEN + (size_t)h0 * S_LEN;

    float acc[4][4][4];
#pragma unroll
    for (int i = 0; i < 4; i++)
#pragma unroll
        for (int j = 0; j < 4; j++)
#pragma unroll
            for (int r = 0; r < 4; r++) acc[i][j][r] = 0.f;

    gemm_main(Abase, S_LEN, Bbase, S_LEN, S_LEN, smem, acc);

    const int tid = threadIdx.x, wid = tid >> 5, lane = tid & 31;
    const int wm = (wid >> 2) * 64, wn = (wid & 3) * 32;
    const int g = lane >> 2, tig = lane & 3;
#pragma unroll
    for (int mt = 0; mt < 4; mt++)
#pragma unroll
        for (int nt = 0; nt < 4; nt++) {
            const int row = q0 + wm + mt * 16 + g;         // s (query)
            const int col = h0 + wn + nt * 8 + tig * 2;    // h
            float* d0 = out + (size_t)row * (BATCH * HDIM) + (size_t)b * HDIM + col;
            float* d1 = out + (size_t)(row + 8) * (BATCH * HDIM) + (size_t)b * HDIM + col;
            *(float2*)d0 = make_float2(acc[mt][nt][0], acc[mt][nt][1]);
            *(float2*)d1 = make_float2(acc[mt][nt][2], acc[mt][nt][3]);
        }
}

// =====================================================================
extern "C" void kernel_launch(void* const* d_in, const int* in_sizes, int n_in,
                              void* d_out, int out_size)
{
    const float* x    = (const float*)d_in[0];
    const float* ssm  = (const float*)d_in[1];
    const float* Wq   = (const float*)d_in[2];
    const float* bq   = (const float*)d_in[3];
    const float* Wk   = (const float*)d_in[4];
    const float* bk   = (const float*)d_in[5];
    const float* Wv   = (const float*)d_in[6];
    const float* bv   = (const float*)d_in[7];
    const float* beta = (const float*)d_in[8];
    float* out = (float*)d_out;

    cudaFuncSetAttribute(proj_mma,   cudaFuncAttributeMaxDynamicSharedMemorySize, SMEM_BYTES);
    cudaFuncSetAttribute(scores_mma, cudaFuncAttributeMaxDynamicSharedMemorySize, SMEM_BYTES);
    cudaFuncSetAttribute(out_mma,    cudaFuncAttributeMaxDynamicSharedMemorySize, SMEM_BYTES);

    dim3 blk(256);
    proj_mma<<<dim3(HDIM / 128, MROWS / 128, 3), blk, SMEM_BYTES>>>(
        x, Wq, Wk, Wv, bq, bk, bv);

    transpose_v<<<dim3(S_LEN / 32, HDIM / 32, BATCH), dim3(32, 8)>>>();

    scores_mma<<<dim3(S_LEN / 128, S_LEN / 128, BATCH), blk, SMEM_BYTES>>>(ssm, beta);

    softmax_kernel<<<MROWS, blk>>>();

    out_mma<<<dim3(HDIM / 128, S_LEN / 128, BATCH), blk, SMEM_BYTES>>>(out);
}

// round 15
// speedup vs baseline: 2.9254x; 1.2210x over previous
#include <cuda_runtime.h>
#include <cuda_fp16.h>
#include <cstdint>

// ---------------- problem constants ----------------
#define S_LEN 2048
#define BATCH 4
#define HDIM  1024
#define MROWS (BATCH*S_LEN)        // 8192
#define SCALE_INV 0.03125f         // 1/sqrt(1024)

// ---------------- scratch (device globals; allocation-guard-safe) ----------
__device__ __half g_xh [(size_t)MROWS*HDIM];        // x hi limb  [B*S, H]
__device__ __half g_xl [(size_t)MROWS*HDIM];        // x lo limb
__device__ __half g_w16[3][(size_t)HDIM*HDIM];      // Wq/Wk/Wv fp16 [O, H]
__device__ __half g_qh [(size_t)MROWS*HDIM];        // Q hi limb  [B*S, H]
__device__ __half g_ql [(size_t)MROWS*HDIM];        // Q lo limb
__device__ __half g_k16[(size_t)MROWS*HDIM];        // K fp16     [B*S, H]
__device__ float  g_V  [(size_t)MROWS*HDIM];        // V fp32     [B,S,H]
__device__ __half g_vt [(size_t)BATCH*HDIM*S_LEN];  // V^T fp16   [B,H,S]
__device__ float  g_P  [(size_t)BATCH*S_LEN*S_LEN]; // scores fp32 [B,S,S]
__device__ __half g_p16[(size_t)MROWS*S_LEN];       // softmax(P) fp16

// ---------------- smem layout ----------------
// fp16 rows: 32 elems = 64 B data, stride 80 B (conflict-free, R12-validated).
// Planes per stage: A_hi | A_lo | B   (2-pass)  or  A | B (1-pass).
#define ROWB   80
#define PLANE  10240          // 128 rows * 80 B
#define SMEM2  (2 * 3 * PLANE)   // 61440 (double-buffered, 3 planes)
#define SMEM1  (2 * 2 * PLANE)   // 40960 (double-buffered, 2 planes)

// ---------------- helpers ----------------
__device__ __forceinline__ uint32_t smem_u32(const void* p) {
    uint32_t a;
    asm("{ .reg .u64 t; cvta.to.shared.u64 t, %1; cvt.u32.u64 %0, t; }" : "=r"(a) : "l"(p));
    return a;
}
__device__ __forceinline__ uint32_t lds32(uint32_t a) {
    uint32_t v; asm volatile("ld.shared.b32 %0, [%1];" : "=r"(v) : "r"(a)); return v;
}
#define STS128(v, addr) \
    asm volatile("st.shared.v4.b32 [%0], {%1, %2, %3, %4};" \
        :: "r"(addr), "r"((v).x), "r"((v).y), "r"((v).z), "r"((v).w) : "memory")

// m16n8k16 row.col fp16 -> f32 accumulate (Ampere-compatible PTX)
#define MMA_F16(d, a, b) \
    asm volatile("mma.sync.aligned.m16n8k16.row.col.f32.f16.f16.f32 " \
        "{%0,%1,%2,%3}, {%4,%5,%6,%7}, {%8,%9}, {%0,%1,%2,%3};" \
        : "+f"((d)[0]), "+f"((d)[1]), "+f"((d)[2]), "+f"((d)[3]) \
        : "r"((a)[0]), "r"((a)[1]), "r"((a)[2]), "r"((a)[3]), \
          "r"((b)[0]), "r"((b)[1]))

// ---------------- generic 128x128 GEMM mainloop, fp16-resident operands ----
// NP = 2: acc += (A_hi + A_lo).B   (fp32-emulated, A exact to ~2^-22)
// NP = 1: acc += A.B               (plain fp16 pass)
// Warp layout 2(M) x 4(N), warp tile 64x32, k-tile 32, double buffer,
// register-prefetch loader (R12/R14-proven skeleton).
template<int NP>
__device__ __forceinline__ void gemm_h(
    const __half* __restrict__ Ah, const __half* __restrict__ Al,
    const __half* __restrict__ Bh, int lda, int ldb,
    int K, char* smem, float acc[4][4][4])
{
    const int STAGE = (NP + 1) * PLANE;
    const int P_AL  = PLANE;                  // only used when NP == 2
    const int P_B   = NP * PLANE;

    const int tid  = threadIdx.x;
    const int wid  = tid >> 5, lane = tid & 31;
    const int wm   = (wid >> 2) * 64;
    const int wn   = (wid & 3) * 32;
    const int g    = lane >> 2, tig = lane & 3;
    const uint32_t sb = smem_u32(smem);

    // loader: 2 threads per row, 32 B (16 halfs) each
    const int r = tid >> 1, q = tid & 1;
    const char* aH = (const char*)(Ah + (size_t)r * lda) + q * 32;
    const char* aL = (const char*)(((NP == 2) ? Al : Ah) + (size_t)r * lda) + q * 32;
    const char* bP = (const char*)(Bh + (size_t)r * ldb) + q * 32;
    const uint32_t st = sb + r * ROWB + q * 32;

    const uint32_t rdA = sb + (wm + g) * ROWB + tig * 4;
    const uint32_t rdB = sb + P_B + (wn + g) * ROWB + tig * 4;

    uint4 vh[2], vl[2], vb[2];
#pragma unroll
    for (int j = 0; j < 2; j++) {
        vh[j] = *(const uint4*)(aH + j * 16);
        if (NP == 2) vl[j] = *(const uint4*)(aL + j * 16);
        vb[j] = *(const uint4*)(bP + j * 16);
    }
    STS128(vh[0], st);            STS128(vh[1], st + 16);
    if (NP == 2) { STS128(vl[0], st + P_AL); STS128(vl[1], st + P_AL + 16); }
    STS128(vb[0], st + P_B);      STS128(vb[1], st + P_B + 16);
    __syncthreads();

    const int T = K >> 5;                       // 32-wide K tiles (64 B rows)
    for (int t = 0; t < T; ++t) {
        const uint32_t so = (uint32_t)(t & 1) * STAGE;

        if (t + 1 < T) {                        // prefetch next tile into regs
            const int kb = (t + 1) << 6;        // byte offset: 32 halfs = 64 B
#pragma unroll
            for (int j = 0; j < 2; j++) {
                vh[j] = *(const uint4*)(aH + kb + j * 16);
                if (NP == 2) vl[j] = *(const uint4*)(aL + kb + j * 16);
                vb[j] = *(const uint4*)(bP + kb + j * 16);
            }
        }

#pragma unroll
        for (int ks = 0; ks < 2; ks++) {        // two k16 steps per tile
            const uint32_t co = so + ks * 32;   // 16 fp16 = 32 B
            uint32_t ah[4][4], al[4][4], bh[4][2];
#pragma unroll
            for (int mt = 0; mt < 4; mt++) {
                const uint32_t ba = rdA + co + mt * (16 * ROWB);
                ah[mt][0] = lds32(ba);
                ah[mt][1] = lds32(ba + 8 * ROWB);
                ah[mt][2] = lds32(ba + 16);
                ah[mt][3] = lds32(ba + 8 * ROWB + 16);
                if (NP == 2) {
                    al[mt][0] = lds32(ba + P_AL);
                    al[mt][1] = lds32(ba + P_AL + 8 * ROWB);
                    al[mt][2] = lds32(ba + P_AL + 16);
                    al[mt][3] = lds32(ba + P_AL + 8 * ROWB + 16);
                }
            }
#pragma unroll
            for (int nt = 0; nt < 4; nt++) {
                const uint32_t bb = rdB + co + nt * (8 * ROWB);
                bh[nt][0] = lds32(bb);
                bh[nt][1] = lds32(bb + 16);
            }
#pragma unroll
            for (int mt = 0; mt < 4; mt++)
#pragma unroll
                for (int nt = 0; nt < 4; nt++) {
                    MMA_F16(acc[mt][nt], ah[mt], bh[nt]);
                    if (NP == 2) MMA_F16(acc[mt][nt], al[mt], bh[nt]);
                }
        }

        if (t + 1 < T) {
            const uint32_t st2 = st + (uint32_t)((t + 1) & 1) * STAGE;
            STS128(vh[0], st2);            STS128(vh[1], st2 + 16);
            if (NP == 2) { STS128(vl[0], st2 + P_AL); STS128(vl[1], st2 + P_AL + 16); }
            STS128(vb[0], st2 + P_B);      STS128(vb[1], st2 + P_B + 16);
        }
        __syncthreads();
    }
}

#define ACC_INIT(acc) do {                                \
    _Pragma("unroll") for (int i = 0; i < 4; i++)         \
    _Pragma("unroll") for (int j = 0; j < 4; j++)         \
    _Pragma("unroll") for (int r = 0; r < 4; r++) acc[i][j][r] = 0.f; \
} while (0)

// Output coords for acc[mt][nt]:
//   row = m0 + wm + mt*16 + g (+8 for regs 2,3); col = n0 + wn + nt*8 + tig*2

// =====================================================================
// Prep 1: split x (reordered [S,B,H] -> [B*S,H]) into fp16 hi/lo planes.
// =====================================================================
__global__ void __launch_bounds__(256) split_x(const float* __restrict__ x)
{
    const int row = blockIdx.x;                 // b*S + s
    const int b = row >> 11, s = row & (S_LEN - 1);
    const float2* src = (const float2*)x + ((size_t)s * BATCH + b) * (HDIM / 2);
    __half2* dh = (__half2*)g_xh + (size_t)row * (HDIM / 2);
    __half2* dl = (__half2*)g_xl + (size_t)row * (HDIM / 2);
    const int tid = threadIdx.x;
#pragma unroll
    for (int i = 0; i < 2; i++) {
        const int idx = tid + (i << 8);
        float2 v = src[idx];
        __half2 h = __floats2half2_rn(v.x, v.y);
        float2 hf = __half22float2(h);
        dh[idx] = h;
        dl[idx] = __floats2half2_rn(v.x - hf.x, v.y - hf.y);
    }
}

// =====================================================================
// Prep 2: W -> fp16 (single rounding; B-side of proj GEMM). grid (H, 3)
// =====================================================================
__global__ void __launch_bounds__(256) cvt_w(
    const float* __restrict__ Wq, const float* __restrict__ Wk,
    const float* __restrict__ Wv)
{
    const int row = blockIdx.x, z = blockIdx.y;
    const float* W = (z == 0) ? Wq : (z == 1) ? Wk : Wv;
    const float2* src = (const float2*)W + (size_t)row * (HDIM / 2);
    __half2* dst = (__half2*)&g_w16[z][0] + (size_t)row * (HDIM / 2);
    const int tid = threadIdx.x;
#pragma unroll
    for (int i = 0; i < 2; i++) {
        const int idx = tid + (i << 8);
        float2 v = src[idx];
        dst[idx] = __floats2half2_rn(v.x, v.y);
    }
}

// =====================================================================
// Kernel 1: fused QKV projection, 2-pass. grid (8, 64, 3).
// z=0 -> Q (hi/lo fp16 planes), z=1 -> K (fp16), z=2 -> V (fp32).
// =====================================================================
__global__ void __launch_bounds__(256, 1) proj_mma(
    const float* __restrict__ bq, const float* __restrict__ bk,
    const float* __restrict__ bv)
{
    extern __shared__ char smem[];
    const int m0 = blockIdx.y * 128;
    const int n0 = blockIdx.x * 128;
    const int z  = blockIdx.z;
    const float* bias = (z == 0) ? bq : (z == 1) ? bk : bv;

    float acc[4][4][4];
    ACC_INIT(acc);
    gemm_h<2>(g_xh + (size_t)m0 * HDIM, g_xl + (size_t)m0 * HDIM,
              &g_w16[z][(size_t)n0 * HDIM], HDIM, HDIM, HDIM, smem, acc);

    const int tid = threadIdx.x, wid = tid >> 5, lane = tid & 31;
    const int wm = (wid >> 2) * 64, wn = (wid & 3) * 32;
    const int g = lane >> 2, tig = lane & 3;
#pragma unroll
    for (int mt = 0; mt < 4; mt++)
#pragma unroll
        for (int nt = 0; nt < 4; nt++) {
            const int row = m0 + wm + mt * 16 + g;
            const int col = n0 + wn + nt * 8 + tig * 2;
            const float2 bv2 = *(const float2*)(bias + col);
            const float a0 = acc[mt][nt][0] + bv2.x, a1 = acc[mt][nt][1] + bv2.y;
            const float a2 = acc[mt][nt][2] + bv2.x, a3 = acc[mt][nt][3] + bv2.y;
            const size_t i0 = (size_t)row * HDIM + col;
            const size_t i1 = (size_t)(row + 8) * HDIM + col;
            if (z == 0) {
                __half2 h0 = __floats2half2_rn(a0, a1);
                __half2 h1 = __floats2half2_rn(a2, a3);
                float2 f0 = __half22float2(h0), f1 = __half22float2(h1);
                *(__half2*)(g_qh + i0) = h0;
                *(__half2*)(g_qh + i1) = h1;
                *(__half2*)(g_ql + i0) = __floats2half2_rn(a0 - f0.x, a1 - f0.y);
                *(__half2*)(g_ql + i1) = __floats2half2_rn(a2 - f1.x, a3 - f1.y);
            } else if (z == 1) {
                *(__half2*)(g_k16 + i0) = __floats2half2_rn(a0, a1);
                *(__half2*)(g_k16 + i1) = __floats2half2_rn(a2, a3);
            } else {
                *(float2*)(g_V + i0) = make_float2(a0, a1);
                *(float2*)(g_V + i1) = make_float2(a2, a3);
            }
        }
}

// =====================================================================
// Kernel 2: V transpose + fp16 cvt:  g_vt[b][h][s] = fp16(g_V[b][s][h])
// =====================================================================
__global__ void __launch_bounds__(256) transpose_v()
{
    __shared__ float tile[32][33];
    const int b  = blockIdx.z;
    const int s0 = blockIdx.x * 32;
    const int h0 = blockIdx.y * 32;
    const int tx = threadIdx.x, ty = threadIdx.y;
    const float* src = g_V + ((size_t)b * S_LEN + s0) * HDIM + h0;
#pragma unroll
    for (int i = 0; i < 32; i += 8)
        tile[ty + i][tx] = src[(size_t)(ty + i) * HDIM + tx];
    __syncthreads();
    __half* dst = g_vt + ((size_t)b * HDIM + h0) * S_LEN + s0;
#pragma unroll
    for (int i = 0; i < 32; i += 8)
        dst[(size_t)(ty + i) * S_LEN + tx] = __float2half_rn(tile[tx][ty + i]);
}

// =====================================================================
// Kernel 3: scores, 2-pass.  P = (Q.K^T)/32 + beta*ssm  (fp32). grid (16,16,4)
// =====================================================================
__global__ void __launch_bounds__(256, 1) scores_mma(
    const float* __restrict__ ssm, const float* __restrict__ beta_p)
{
    extern __shared__ char smem[];
    const int q0  = blockIdx.y * 128;
    const int kk0 = blockIdx.x * 128;
    const int b   = blockIdx.z;

    float acc[4][4][4];
    ACC_INIT(acc);
    gemm_h<2>(g_qh + (size_t)(b * S_LEN + q0) * HDIM,
              g_ql + (size_t)(b * S_LEN + q0) * HDIM,
              g_k16 + (size_t)(b * S_LEN + kk0) * HDIM,
              HDIM, HDIM, HDIM, smem, acc);

    const float beta = __ldg(beta_p);
    const int tid = threadIdx.x, wid = tid >> 5, lane = tid & 31;
    const int wm = (wid >> 2) * 64, wn = (wid & 3) * 32;
    const int g = lane >> 2, tig = lane & 3;
    float*       Pb = g_P + (size_t)b * S_LEN * S_LEN;
    const float* Sb = ssm + (size_t)b * S_LEN * S_LEN;
#pragma unroll
    for (int mt = 0; mt < 4; mt++)
#pragma unroll
        for (int nt = 0; nt < 4; nt++) {
            const int row = q0 + wm + mt * 16 + g;
            const int col = kk0 + wn + nt * 8 + tig * 2;
            const float2 s0 = *(const float2*)(Sb + (size_t)row * S_LEN + col);
            const float2 s1 = *(const float2*)(Sb + (size_t)(row + 8) * S_LEN + col);
            *(float2*)(Pb + (size_t)row * S_LEN + col) =
                make_float2(acc[mt][nt][0] * SCALE_INV + beta * s0.x,
                            acc[mt][nt][1] * SCALE_INV + beta * s0.y);
            *(float2*)(Pb + (size_t)(row + 8) * S_LEN + col) =
                make_float2(acc[mt][nt][2] * SCALE_INV + beta * s1.x,
                            acc[mt][nt][3] * SCALE_INV + beta * s1.y);
        }
}

// =====================================================================
// Kernel 4: softmax (fp32 in) + fp16 quantization of probabilities.
// =====================================================================
__global__ void __launch_bounds__(256) softmax_kernel()
{
    const int row = blockIdx.x;
    const float2* p = (const float2*)(g_P + (size_t)row * S_LEN);
    __half2* d = (__half2*)(g_p16 + (size_t)row * S_LEN);
    const int tid = threadIdx.x;

    float2 v[4];
    float mx = -1e30f;
#pragma unroll
    for (int i = 0; i < 4; i++) {
        v[i] = p[tid + (i << 8)];
        mx = fmaxf(mx, fmaxf(v[i].x, v[i].y));
    }
#pragma unroll
    for (int o = 16; o; o >>= 1) mx = fmaxf(mx, __shfl_xor_sync(0xffffffffu, mx, o));
    __shared__ float sred[8];
    if ((tid & 31) == 0) sred[tid >> 5] = mx;
    __syncthreads();
#pragma unroll
    for (int i = 0; i < 8; i++) mx = fmaxf(mx, sred[i]);

    float sum = 0.f;
#pragma unroll
    for (int i = 0; i < 4; i++) {
        v[i].x = __expf(v[i].x - mx); v[i].y = __expf(v[i].y - mx);
        sum += v[i].x + v[i].y;
    }
#pragma unroll
    for (int o = 16; o; o >>= 1) sum += __shfl_xor_sync(0xffffffffu, sum, o);
    __syncthreads();
    if ((tid & 31) == 0) sred[tid >> 5] = sum;
    __syncthreads();
    sum = 0.f;
#pragma unroll
    for (int i = 0; i < 8; i++) sum += sred[i];

    const float inv = 1.0f / sum;
#pragma unroll
    for (int i = 0; i < 4; i++)
        d[tid + (i << 8)] = __floats2half2_rn(v[i].x * inv, v[i].y * inv);
}

// =====================================================================
// Kernel 5: out = P.V, single-pass fp16.  grid (8, 16, 4)
// =====================================================================
__global__ void __launch_bounds__(256, 1) out_mma(float* __restrict__ out)
{
    extern __shared__ char smem[];
    const int q0 = blockIdx.y * 128;
    const int h0 = blockIdx.x * 128;
    const int b  = blockIdx.z;

    float acc[4][4][4];
    ACC_INIT(acc);
    gemm_h<1>(g_p16 + (size_t)(b * S_LEN + q0) * S_LEN, (const __half*)0,
              g_vt + (size_t)(b * HDIM + h0) * S_LEN,
              S_LEN, S_LEN, S_LEN, smem, acc);

    const int tid = threadIdx.x, wid = tid >> 5, lane = tid & 31;
    const int wm = (wid >> 2) * 64, wn = (wid & 3) * 32;
    const int g = lane >> 2, tig = lane & 3;
#pragma unroll
    for (int mt = 0; mt < 4; mt++)
#pragma unroll
        for (int nt = 0; nt < 4; nt++) {
            const int row = q0 + wm + mt * 16 + g;         // s (query)
            const int col = h0 + wn + nt * 8 + tig * 2;    // h
            float* d0 = out + (size_t)row * (BATCH * HDIM) + (size_t)b * HDIM + col;
            float* d1 = out + (size_t)(row + 8) * (BATCH * HDIM) + (size_t)b * HDIM + col;
            *(float2*)d0 = make_float2(acc[mt][nt][0], acc[mt][nt][1]);
            *(float2*)d1 = make_float2(acc[mt][nt][2], acc[mt][nt][3]);
        }
}

// =====================================================================
extern "C" void kernel_launch(void* const* d_in, const int* in_sizes, int n_in,
                              void* d_out, int out_size)
{
    const float* x    = (const float*)d_in[0];
    const float* ssm  = (const float*)d_in[1];
    const float* Wq   = (const float*)d_in[2];
    const float* bq   = (const float*)d_in[3];
    const float* Wk   = (const float*)d_in[4];
    const float* bk   = (const float*)d_in[5];
    const float* Wv   = (const float*)d_in[6];
    const float* bv   = (const float*)d_in[7];
    const float* beta = (const float*)d_in[8];
    float* out = (float*)d_out;

    cudaFuncSetAttribute(proj_mma,   cudaFuncAttributeMaxDynamicSharedMemorySize, SMEM2);
    cudaFuncSetAttribute(scores_mma, cudaFuncAttributeMaxDynamicSharedMemorySize, SMEM2);
    cudaFuncSetAttribute(out_mma,    cudaFuncAttributeMaxDynamicSharedMemorySize, SMEM1);

    dim3 blk(256);
    split_x<<<MROWS, blk>>>(x);
    cvt_w<<<dim3(HDIM, 3), blk>>>(Wq, Wk, Wv);

    proj_mma<<<dim3(HDIM / 128, MROWS / 128, 3), blk, SMEM2>>>(bq, bk, bv);

    transpose_v<<<dim3(S_LEN / 32, HDIM / 32, BATCH), dim3(32, 8)>>>();

    scores_mma<<<dim3(S_LEN / 128, S_LEN / 128, BATCH), blk, SMEM2>>>(ssm, beta);

    softmax_kernel<<<MROWS, blk>>>();

    out_mma<<<dim3(HDIM / 128, S_LEN / 128, BATCH), blk, SMEM1>>>(out);
}

// round 16
// speedup vs baseline: 4.0614x; 1.3883x over previous
#include <cuda_runtime.h>
#include <cuda_fp16.h>
#include <cstdint>

// ---------------- problem constants ----------------
#define S_LEN 2048
#define BATCH 4
#define HDIM  1024
#define MROWS (BATCH*S_LEN)        // 8192
#define SCALE_INV 0.03125f         // 1/sqrt(1024)

// ---------------- scratch (device globals; allocation-guard-safe) ----------
__device__ __half g_x16[(size_t)MROWS*HDIM];        // x fp16   [B*S, H]
__device__ __half g_w16[3][(size_t)HDIM*HDIM];      // Wq/Wk/Wv fp16 [O, H]
__device__ __half g_q16[(size_t)MROWS*HDIM];        // Q fp16   [B*S, H]
__device__ __half g_k16[(size_t)MROWS*HDIM];        // K fp16   [B*S, H]
__device__ __half g_v16[(size_t)MROWS*HDIM];        // V fp16   [B,S,H]
__device__ __half g_vt [(size_t)BATCH*HDIM*S_LEN];  // V^T fp16 [B,H,S]
__device__ float  g_P  [(size_t)BATCH*S_LEN*S_LEN]; // scores fp32 [B,S,S]
__device__ __half g_p16[(size_t)MROWS*S_LEN];       // softmax(P) fp16

// ---------------- smem layout ----------------
// fp16 rows: 32 elems = 64 B data, stride 80 B (conflict-free, validated).
// Planes per stage: A | B. Double buffered.
#define ROWB   80
#define PLANE  10240              // 128 rows * 80 B
#define SMEM1  (2 * 2 * PLANE)    // 40960

// ---------------- helpers ----------------
__device__ __forceinline__ uint32_t smem_u32(const void* p) {
    uint32_t a;
    asm("{ .reg .u64 t; cvta.to.shared.u64 t, %1; cvt.u32.u64 %0, t; }" : "=r"(a) : "l"(p));
    return a;
}
__device__ __forceinline__ uint32_t lds32(uint32_t a) {
    uint32_t v; asm volatile("ld.shared.b32 %0, [%1];" : "=r"(v) : "r"(a)); return v;
}
#define STS128(v, addr) \
    asm volatile("st.shared.v4.b32 [%0], {%1, %2, %3, %4};" \
        :: "r"(addr), "r"((v).x), "r"((v).y), "r"((v).z), "r"((v).w) : "memory")

// m16n8k16 row.col fp16 -> f32 accumulate (Ampere-compatible PTX)
#define MMA_F16(d, a, b) \
    asm volatile("mma.sync.aligned.m16n8k16.row.col.f32.f16.f16.f32 " \
        "{%0,%1,%2,%3}, {%4,%5,%6,%7}, {%8,%9}, {%0,%1,%2,%3};" \
        : "+f"((d)[0]), "+f"((d)[1]), "+f"((d)[2]), "+f"((d)[3]) \
        : "r"((a)[0]), "r"((a)[1]), "r"((a)[2]), "r"((a)[3]), \
          "r"((b)[0]), "r"((b)[1]))

// ---------------- generic 128x128 single-pass fp16 GEMM mainloop ----------
// acc += A.B^T (K-major both sides). Warp layout 2(M) x 4(N), warp tile 64x32,
// k-tile 32, double buffer, register-prefetch loader (R12/R15-proven skeleton).
__device__ __forceinline__ void gemm_h(
    const __half* __restrict__ A, const __half* __restrict__ B,
    int lda, int ldb, int K, char* smem, float acc[4][4][4])
{
    const int STAGE = 2 * PLANE;
    const int P_B   = PLANE;

    const int tid  = threadIdx.x;
    const int wid  = tid >> 5, lane = tid & 31;
    const int wm   = (wid >> 2) * 64;
    const int wn   = (wid & 3) * 32;
    const int g    = lane >> 2, tig = lane & 3;
    const uint32_t sb = smem_u32(smem);

    // loader: 2 threads per row, 32 B (16 halfs) each
    const int r = tid >> 1, q = tid & 1;
    const char* aP = (const char*)(A + (size_t)r * lda) + q * 32;
    const char* bP = (const char*)(B + (size_t)r * ldb) + q * 32;
    const uint32_t st = sb + r * ROWB + q * 32;

    const uint32_t rdA = sb + (wm + g) * ROWB + tig * 4;
    const uint32_t rdB = sb + P_B + (wn + g) * ROWB + tig * 4;

    uint4 va[2], vb[2];
#pragma unroll
    for (int j = 0; j < 2; j++) {
        va[j] = *(const uint4*)(aP + j * 16);
        vb[j] = *(const uint4*)(bP + j * 16);
    }
    STS128(va[0], st);       STS128(va[1], st + 16);
    STS128(vb[0], st + P_B); STS128(vb[1], st + P_B + 16);
    __syncthreads();

    const int T = K >> 5;                       // 32-wide K tiles (64 B rows)
    for (int t = 0; t < T; ++t) {
        const uint32_t so = (uint32_t)(t & 1) * STAGE;

        if (t + 1 < T) {                        // prefetch next tile into regs
            const int kb = (t + 1) << 6;        // 32 halfs = 64 B
#pragma unroll
            for (int j = 0; j < 2; j++) {
                va[j] = *(const uint4*)(aP + kb + j * 16);
                vb[j] = *(const uint4*)(bP + kb + j * 16);
            }
        }

#pragma unroll
        for (int ks = 0; ks < 2; ks++) {        // two k16 steps per tile
            const uint32_t co = so + ks * 32;   // 16 fp16 = 32 B
            uint32_t ah[4][4], bh[4][2];
#pragma unroll
            for (int mt = 0; mt < 4; mt++) {
                const uint32_t ba = rdA + co + mt * (16 * ROWB);
                ah[mt][0] = lds32(ba);
                ah[mt][1] = lds32(ba + 8 * ROWB);
                ah[mt][2] = lds32(ba + 16);
                ah[mt][3] = lds32(ba + 8 * ROWB + 16);
            }
#pragma unroll
            for (int nt = 0; nt < 4; nt++) {
                const uint32_t bb = rdB + co + nt * (8 * ROWB);
                bh[nt][0] = lds32(bb);
                bh[nt][1] = lds32(bb + 16);
            }
#pragma unroll
            for (int mt = 0; mt < 4; mt++)
#pragma unroll
                for (int nt = 0; nt < 4; nt++)
                    MMA_F16(acc[mt][nt], ah[mt], bh[nt]);
        }

        if (t + 1 < T) {
            const uint32_t st2 = st + (uint32_t)((t + 1) & 1) * STAGE;
            STS128(va[0], st2);       STS128(va[1], st2 + 16);
            STS128(vb[0], st2 + P_B); STS128(vb[1], st2 + P_B + 16);
        }
        __syncthreads();
    }
}

#define ACC_INIT(acc) do {                                \
    _Pragma("unroll") for (int i = 0; i < 4; i++)         \
    _Pragma("unroll") for (int j = 0; j < 4; j++)         \
    _Pragma("unroll") for (int r = 0; r < 4; r++) acc[i][j][r] = 0.f; \
} while (0)

// Output coords for acc[mt][nt]:
//   row = m0 + wm + mt*16 + g (+8 for regs 2,3); col = n0 + wn + nt*8 + tig*2

// =====================================================================
// Prep 1: x [S,B,H] -> fp16 [B*S,H] (reorder + single rounding)
// =====================================================================
__global__ void __launch_bounds__(256) cvt_x(const float* __restrict__ x)
{
    const int row = blockIdx.x;                 // b*S + s
    const int b = row >> 11, s = row & (S_LEN - 1);
    const float2* src = (const float2*)x + ((size_t)s * BATCH + b) * (HDIM / 2);
    __half2* dst = (__half2*)g_x16 + (size_t)row * (HDIM / 2);
    const int tid = threadIdx.x;
#pragma unroll
    for (int i = 0; i < 2; i++) {
        const int idx = tid + (i << 8);
        float2 v = src[idx];
        dst[idx] = __floats2half2_rn(v.x, v.y);
    }
}

// =====================================================================
// Prep 2: W -> fp16. grid (H, 3)
// =====================================================================
__global__ void __launch_bounds__(256) cvt_w(
    const float* __restrict__ Wq, const float* __restrict__ Wk,
    const float* __restrict__ Wv)
{
    const int row = blockIdx.x, z = blockIdx.y;
    const float* W = (z == 0) ? Wq : (z == 1) ? Wk : Wv;
    const float2* src = (const float2*)W + (size_t)row * (HDIM / 2);
    __half2* dst = (__half2*)&g_w16[z][0] + (size_t)row * (HDIM / 2);
    const int tid = threadIdx.x;
#pragma unroll
    for (int i = 0; i < 2; i++) {
        const int idx = tid + (i << 8);
        float2 v = src[idx];
        dst[idx] = __floats2half2_rn(v.x, v.y);
    }
}

// =====================================================================
// Kernel 1: fused QKV projection, single-pass. grid (8, 64, 3).
// out fp16: z=0 -> Q, z=1 -> K, z=2 -> V.
// =====================================================================
__global__ void __launch_bounds__(256, 1) proj_mma(
    const float* __restrict__ bq, const float* __restrict__ bk,
    const float* __restrict__ bv)
{
    extern __shared__ char smem[];
    const int m0 = blockIdx.y * 128;
    const int n0 = blockIdx.x * 128;
    const int z  = blockIdx.z;
    const float* bias = (z == 0) ? bq : (z == 1) ? bk : bv;
    __half* outp      = (z == 0) ? g_q16 : (z == 1) ? g_k16 : g_v16;

    float acc[4][4][4];
    ACC_INIT(acc);
    gemm_h(g_x16 + (size_t)m0 * HDIM, &g_w16[z][(size_t)n0 * HDIM],
           HDIM, HDIM, HDIM, smem, acc);

    const int tid = threadIdx.x, wid = tid >> 5, lane = tid & 31;
    const int wm = (wid >> 2) * 64, wn = (wid & 3) * 32;
    const int g = lane >> 2, tig = lane & 3;
#pragma unroll
    for (int mt = 0; mt < 4; mt++)
#pragma unroll
        for (int nt = 0; nt < 4; nt++) {
            const int row = m0 + wm + mt * 16 + g;
            const int col = n0 + wn + nt * 8 + tig * 2;
            const float2 bv2 = *(const float2*)(bias + col);
            *(__half2*)(outp + (size_t)row * HDIM + col) =
                __floats2half2_rn(acc[mt][nt][0] + bv2.x, acc[mt][nt][1] + bv2.y);
            *(__half2*)(outp + (size_t)(row + 8) * HDIM + col) =
                __floats2half2_rn(acc[mt][nt][2] + bv2.x, acc[mt][nt][3] + bv2.y);
        }
}

// =====================================================================
// Kernel 2: V transpose (fp16 -> fp16):  g_vt[b][h][s] = g_v16[b][s][h]
// =====================================================================
__global__ void __launch_bounds__(256) transpose_v()
{
    __shared__ __half tile[32][40];   // 80 B rows: conflict-free both phases
    const int b  = blockIdx.z;
    const int s0 = blockIdx.x * 32;
    const int h0 = blockIdx.y * 32;
    const int tx = threadIdx.x, ty = threadIdx.y;
    const __half* src = g_v16 + ((size_t)b * S_LEN + s0) * HDIM + h0;
#pragma unroll
    for (int i = 0; i < 32; i += 8)
        tile[ty + i][tx] = src[(size_t)(ty + i) * HDIM + tx];
    __syncthreads();
    __half* dst = g_vt + ((size_t)b * HDIM + h0) * S_LEN + s0;
#pragma unroll
    for (int i = 0; i < 32; i += 8)
        dst[(size_t)(ty + i) * S_LEN + tx] = tile[tx][ty + i];
}

// =====================================================================
// Kernel 3: scores, single-pass.  P = (Q.K^T)/32 + beta*ssm (fp32).
// grid (16, 16, 4)
// =====================================================================
__global__ void __launch_bounds__(256, 1) scores_mma(
    const float* __restrict__ ssm, const float* __restrict__ beta_p)
{
    extern __shared__ char smem[];
    const int q0  = blockIdx.y * 128;
    const int kk0 = blockIdx.x * 128;
    const int b   = blockIdx.z;

    float acc[4][4][4];
    ACC_INIT(acc);
    gemm_h(g_q16 + (size_t)(b * S_LEN + q0) * HDIM,
           g_k16 + (size_t)(b * S_LEN + kk0) * HDIM,
           HDIM, HDIM, HDIM, smem, acc);

    const float beta = __ldg(beta_p);
    const int tid = threadIdx.x, wid = tid >> 5, lane = tid & 31;
    const int wm = (wid >> 2) * 64, wn = (wid & 3) * 32;
    const int g = lane >> 2, tig = lane & 3;
    float*       Pb = g_P + (size_t)b * S_LEN * S_LEN;
    const float* Sb = ssm + (size_t)b * S_LEN * S_LEN;
#pragma unroll
    for (int mt = 0; mt < 4; mt++)
#pragma unroll
        for (int nt = 0; nt < 4; nt++) {
            const int row = q0 + wm + mt * 16 + g;
            const int col = kk0 + wn + nt * 8 + tig * 2;
            const float2 s0 = *(const float2*)(Sb + (size_t)row * S_LEN + col);
            const float2 s1 = *(const float2*)(Sb + (size_t)(row + 8) * S_LEN + col);
            *(float2*)(Pb + (size_t)row * S_LEN + col) =
                make_float2(acc[mt][nt][0] * SCALE_INV + beta * s0.x,
                            acc[mt][nt][1] * SCALE_INV + beta * s0.y);
            *(float2*)(Pb + (size_t)(row + 8) * S_LEN + col) =
                make_float2(acc[mt][nt][2] * SCALE_INV + beta * s1.x,
                            acc[mt][nt][3] * SCALE_INV + beta * s1.y);
        }
}

// =====================================================================
// Kernel 4: softmax (fp32 in) + fp16 probabilities out.
// =====================================================================
__global__ void __launch_bounds__(256) softmax_kernel()
{
    const int row = blockIdx.x;
    const float2* p = (const float2*)(g_P + (size_t)row * S_LEN);
    __half2* d = (__half2*)(g_p16 + (size_t)row * S_LEN);
    const int tid = threadIdx.x;

    float2 v[4];
    float mx = -1e30f;
#pragma unroll
    for (int i = 0; i < 4; i++) {
        v[i] = p[tid + (i << 8)];
        mx = fmaxf(mx, fmaxf(v[i].x, v[i].y));
    }
#pragma unroll
    for (int o = 16; o; o >>= 1) mx = fmaxf(mx, __shfl_xor_sync(0xffffffffu, mx, o));
    __shared__ float sred[8];
    if ((tid & 31) == 0) sred[tid >> 5] = mx;
    __syncthreads();
#pragma unroll
    for (int i = 0; i < 8; i++) mx = fmaxf(mx, sred[i]);

    float sum = 0.f;
#pragma unroll
    for (int i = 0; i < 4; i++) {
        v[i].x = __expf(v[i].x - mx); v[i].y = __expf(v[i].y - mx);
        sum += v[i].x + v[i].y;
    }
#pragma unroll
    for (int o = 16; o; o >>= 1) sum += __shfl_xor_sync(0xffffffffu, sum, o);
    __syncthreads();
    if ((tid & 31) == 0) sred[tid >> 5] = sum;
    __syncthreads();
    sum = 0.f;
#pragma unroll
    for (int i = 0; i < 8; i++) sum += sred[i];

    const float inv = 1.0f / sum;
#pragma unroll
    for (int i = 0; i < 4; i++)
        d[tid + (i << 8)] = __floats2half2_rn(v[i].x * inv, v[i].y * inv);
}

// =====================================================================
// Kernel 5: out = P.V, single-pass.  grid (8, 16, 4)
// =====================================================================
__global__ void __launch_bounds__(256, 1) out_mma(float* __restrict__ out)
{
    extern __shared__ char smem[];
    const int q0 = blockIdx.y * 128;
    const int h0 = blockIdx.x * 128;
    const int b  = blockIdx.z;

    float acc[4][4][4];
    ACC_INIT(acc);
    gemm_h(g_p16 + (size_t)(b * S_LEN + q0) * S_LEN,
           g_vt + (size_t)(b * HDIM + h0) * S_LEN,
           S_LEN, S_LEN, S_LEN, smem, acc);

    const int tid = threadIdx.x, wid = tid >> 5, lane = tid & 31;
    const int wm = (wid >> 2) * 64, wn = (wid & 3) * 32;
    const int g = lane >> 2, tig = lane & 3;
#pragma unroll
    for (int mt = 0; mt < 4; mt++)
#pragma unroll
        for (int nt = 0; nt < 4; nt++) {
            const int row = q0 + wm + mt * 16 + g;         // s (query)
            const int col = h0 + wn + nt * 8 + tig * 2;    // h
            float* d0 = out + (size_t)row * (BATCH * HDIM) + (size_t)b * HDIM + col;
            float* d1 = out + (size_t)(row + 8) * (BATCH * HDIM) + (size_t)b * HDIM + col;
            *(float2*)d0 = make_float2(acc[mt][nt][0], acc[mt][nt][1]);
            *(float2*)d1 = make_float2(acc[mt][nt][2], acc[mt][nt][3]);
        }
}

// =====================================================================
extern "C" void kernel_launch(void* const* d_in, const int* in_sizes, int n_in,
                              void* d_out, int out_size)
{
    const float* x    = (const float*)d_in[0];
    const float* ssm  = (const float*)d_in[1];
    const float* Wq   = (const float*)d_in[2];
    const float* bq   = (const float*)d_in[3];
    const float* Wk   = (const float*)d_in[4];
    const float* bk   = (const float*)d_in[5];
    const float* Wv   = (const float*)d_in[6];
    const float* bv   = (const float*)d_in[7];
    const float* beta = (const float*)d_in[8];
    float* out = (float*)d_out;

    cudaFuncSetAttribute(proj_mma,   cudaFuncAttributeMaxDynamicSharedMemorySize, SMEM1);
    cudaFuncSetAttribute(scores_mma, cudaFuncAttributeMaxDynamicSharedMemorySize, SMEM1);
    cudaFuncSetAttribute(out_mma,    cudaFuncAttributeMaxDynamicSharedMemorySize, SMEM1);

    dim3 blk(256);
    cvt_x<<<MROWS, blk>>>(x);
    cvt_w<<<dim3(HDIM, 3), blk>>>(Wq, Wk, Wv);

    proj_mma<<<dim3(HDIM / 128, MROWS / 128, 3), blk, SMEM1>>>(bq, bk, bv);

    transpose_v<<<dim3(S_LEN / 32, HDIM / 32, BATCH), dim3(32, 8)>>>();

    scores_mma<<<dim3(S_LEN / 128, S_LEN / 128, BATCH), blk, SMEM1>>>(ssm, beta);

    softmax_kernel<<<MROWS, blk>>>();

    out_mma<<<dim3(HDIM / 128, S_LEN / 128, BATCH), blk, SMEM1>>>(out);
}

// round 17
// speedup vs baseline: 4.7471x; 1.1688x over previous
#include <cuda_runtime.h>
#include <cuda_fp16.h>
#include <cstdint>

// ---------------- problem constants ----------------
#define S_LEN 2048
#define BATCH 4
#define HDIM  1024
#define MROWS (BATCH*S_LEN)        // 8192
#define SCALE_INV 0.03125f         // 1/sqrt(1024)

// ---------------- scratch (device globals; allocation-guard-safe) ----------
__device__ __half g_x16[(size_t)MROWS*HDIM];        // x fp16   [B*S, H]
__device__ __half g_w16[3][(size_t)HDIM*HDIM];      // Wq/Wk/Wv fp16 [O, H]
__device__ __half g_q16[(size_t)MROWS*HDIM];        // Q fp16   [B*S, H]
__device__ __half g_k16[(size_t)MROWS*HDIM];        // K fp16   [B*S, H]
__device__ __half g_v16[(size_t)MROWS*HDIM];        // V fp16   [B,S,H]
__device__ __half g_vt [(size_t)BATCH*HDIM*S_LEN];  // V^T fp16 [B,H,S]
__device__ float  g_P  [(size_t)BATCH*S_LEN*S_LEN]; // scores fp32 [B,S,S]
__device__ __half g_p16[(size_t)MROWS*S_LEN];       // softmax(P) fp16

// ---------------- smem layout ----------------
// fp16 rows: 32 elems = 64 B data, stride 80 B (conflict-free, validated).
// Planes per stage: A | B. Double buffered. 40 KB/CTA -> 2 CTAs/SM.
#define ROWB   80
#define PLANE  10240              // 128 rows * 80 B
#define SMEM1  (2 * 2 * PLANE)    // 40960

// ---------------- helpers ----------------
__device__ __forceinline__ uint32_t smem_u32(const void* p) {
    uint32_t a;
    asm("{ .reg .u64 t; cvta.to.shared.u64 t, %1; cvt.u32.u64 %0, t; }" : "=r"(a) : "l"(p));
    return a;
}
__device__ __forceinline__ uint32_t lds32(uint32_t a) {
    uint32_t v; asm volatile("ld.shared.b32 %0, [%1];" : "=r"(v) : "r"(a)); return v;
}
#define STS128(v, addr) \
    asm volatile("st.shared.v4.b32 [%0], {%1, %2, %3, %4};" \
        :: "r"(addr), "r"((v).x), "r"((v).y), "r"((v).z), "r"((v).w) : "memory")

// m16n8k16 row.col fp16 -> f32 accumulate (Ampere-compatible PTX)
#define MMA_F16(d, a, b) \
    asm volatile("mma.sync.aligned.m16n8k16.row.col.f32.f16.f16.f32 " \
        "{%0,%1,%2,%3}, {%4,%5,%6,%7}, {%8,%9}, {%0,%1,%2,%3};" \
        : "+f"((d)[0]), "+f"((d)[1]), "+f"((d)[2]), "+f"((d)[3]) \
        : "r"((a)[0]), "r"((a)[1]), "r"((a)[2]), "r"((a)[3]), \
          "r"((b)[0]), "r"((b)[1]))

// ---------------- generic 128x128 single-pass fp16 GEMM mainloop ----------
// acc += A.B^T (K-major both sides). Warp layout 2(M) x 4(N), warp tile 64x32,
// k-tile 32, double buffer, register-prefetch loader (proven skeleton).
__device__ __forceinline__ void gemm_h(
    const __half* __restrict__ A, const __half* __restrict__ B,
    int lda, int ldb, int K, char* smem, float acc[4][4][4])
{
    const int STAGE = 2 * PLANE;
    const int P_B   = PLANE;

    const int tid  = threadIdx.x;
    const int wid  = tid >> 5, lane = tid & 31;
    const int wm   = (wid >> 2) * 64;
    const int wn   = (wid & 3) * 32;
    const int g    = lane >> 2, tig = lane & 3;
    const uint32_t sb = smem_u32(smem);

    // loader: 2 threads per row, 32 B (16 halfs) each
    const int r = tid >> 1, q = tid & 1;
    const char* aP = (const char*)(A + (size_t)r * lda) + q * 32;
    const char* bP = (const char*)(B + (size_t)r * ldb) + q * 32;
    const uint32_t st = sb + r * ROWB + q * 32;

    const uint32_t rdA = sb + (wm + g) * ROWB + tig * 4;
    const uint32_t rdB = sb + P_B + (wn + g) * ROWB + tig * 4;

    uint4 va[2], vb[2];
#pragma unroll
    for (int j = 0; j < 2; j++) {
        va[j] = *(const uint4*)(aP + j * 16);
        vb[j] = *(const uint4*)(bP + j * 16);
    }
    STS128(va[0], st);       STS128(va[1], st + 16);
    STS128(vb[0], st + P_B); STS128(vb[1], st + P_B + 16);
    __syncthreads();

    const int T = K >> 5;                       // 32-wide K tiles (64 B rows)
    for (int t = 0; t < T; ++t) {
        const uint32_t so = (uint32_t)(t & 1) * STAGE;

        if (t + 1 < T) {                        // prefetch next tile into regs
            const int kb = (t + 1) << 6;        // 32 halfs = 64 B
#pragma unroll
            for (int j = 0; j < 2; j++) {
                va[j] = *(const uint4*)(aP + kb + j * 16);
                vb[j] = *(const uint4*)(bP + kb + j * 16);
            }
        }

#pragma unroll
        for (int ks = 0; ks < 2; ks++) {        // two k16 steps per tile
            const uint32_t co = so + ks * 32;   // 16 fp16 = 32 B
            uint32_t ah[4][4], bh[4][2];
#pragma unroll
            for (int mt = 0; mt < 4; mt++) {
                const uint32_t ba = rdA + co + mt * (16 * ROWB);
                ah[mt][0] = lds32(ba);
                ah[mt][1] = lds32(ba + 8 * ROWB);
                ah[mt][2] = lds32(ba + 16);
                ah[mt][3] = lds32(ba + 8 * ROWB + 16);
            }
#pragma unroll
            for (int nt = 0; nt < 4; nt++) {
                const uint32_t bb = rdB + co + nt * (8 * ROWB);
                bh[nt][0] = lds32(bb);
                bh[nt][1] = lds32(bb + 16);
            }
#pragma unroll
            for (int mt = 0; mt < 4; mt++)
#pragma unroll
                for (int nt = 0; nt < 4; nt++)
                    MMA_F16(acc[mt][nt], ah[mt], bh[nt]);
        }

        if (t + 1 < T) {
            const uint32_t st2 = st + (uint32_t)((t + 1) & 1) * STAGE;
            STS128(va[0], st2);       STS128(va[1], st2 + 16);
            STS128(vb[0], st2 + P_B); STS128(vb[1], st2 + P_B + 16);
        }
        __syncthreads();
    }
}

#define ACC_INIT(acc) do {                                \
    _Pragma("unroll") for (int i = 0; i < 4; i++)         \
    _Pragma("unroll") for (int j = 0; j < 4; j++)         \
    _Pragma("unroll") for (int r = 0; r < 4; r++) acc[i][j][r] = 0.f; \
} while (0)

// Output coords for acc[mt][nt]:
//   row = m0 + wm + mt*16 + g (+8 for regs 2,3); col = n0 + wn + nt*8 + tig*2

// =====================================================================
// Prep 1: x [S,B,H] -> fp16 [B*S,H] (reorder + single rounding)
// =====================================================================
__global__ void __launch_bounds__(256) cvt_x(const float* __restrict__ x)
{
    const int row = blockIdx.x;                 // b*S + s
    const int b = row >> 11, s = row & (S_LEN - 1);
    const float2* src = (const float2*)x + ((size_t)s * BATCH + b) * (HDIM / 2);
    __half2* dst = (__half2*)g_x16 + (size_t)row * (HDIM / 2);
    const int tid = threadIdx.x;
#pragma unroll
    for (int i = 0; i < 2; i++) {
        const int idx = tid + (i << 8);
        float2 v = src[idx];
        dst[idx] = __floats2half2_rn(v.x, v.y);
    }
}

// =====================================================================
// Prep 2: W -> fp16. grid (H, 3)
// =====================================================================
__global__ void __launch_bounds__(256) cvt_w(
    const float* __restrict__ Wq, const float* __restrict__ Wk,
    const float* __restrict__ Wv)
{
    const int row = blockIdx.x, z = blockIdx.y;
    const float* W = (z == 0) ? Wq : (z == 1) ? Wk : Wv;
    const float2* src = (const float2*)W + (size_t)row * (HDIM / 2);
    __half2* dst = (__half2*)&g_w16[z][0] + (size_t)row * (HDIM / 2);
    const int tid = threadIdx.x;
#pragma unroll
    for (int i = 0; i < 2; i++) {
        const int idx = tid + (i << 8);
        float2 v = src[idx];
        dst[idx] = __floats2half2_rn(v.x, v.y);
    }
}

// =====================================================================
// Kernel 1: fused QKV projection, single-pass. grid (8, 64, 3).
// out fp16: z=0 -> Q, z=1 -> K, z=2 -> V.
// =====================================================================
__global__ void __launch_bounds__(256, 2) proj_mma(
    const float* __restrict__ bq, const float* __restrict__ bk,
    const float* __restrict__ bv)
{
    extern __shared__ char smem[];
    const int m0 = blockIdx.y * 128;
    const int n0 = blockIdx.x * 128;
    const int z  = blockIdx.z;
    const float* bias = (z == 0) ? bq : (z == 1) ? bk : bv;
    __half* outp      = (z == 0) ? g_q16 : (z == 1) ? g_k16 : g_v16;

    float acc[4][4][4];
    ACC_INIT(acc);
    gemm_h(g_x16 + (size_t)m0 * HDIM, &g_w16[z][(size_t)n0 * HDIM],
           HDIM, HDIM, HDIM, smem, acc);

    const int tid = threadIdx.x, wid = tid >> 5, lane = tid & 31;
    const int wm = (wid >> 2) * 64, wn = (wid & 3) * 32;
    const int g = lane >> 2, tig = lane & 3;
#pragma unroll
    for (int mt = 0; mt < 4; mt++)
#pragma unroll
        for (int nt = 0; nt < 4; nt++) {
            const int row = m0 + wm + mt * 16 + g;
            const int col = n0 + wn + nt * 8 + tig * 2;
            const float2 bv2 = *(const float2*)(bias + col);
            *(__half2*)(outp + (size_t)row * HDIM + col) =
                __floats2half2_rn(acc[mt][nt][0] + bv2.x, acc[mt][nt][1] + bv2.y);
            *(__half2*)(outp + (size_t)(row + 8) * HDIM + col) =
                __floats2half2_rn(acc[mt][nt][2] + bv2.x, acc[mt][nt][3] + bv2.y);
        }
}

// =====================================================================
// Kernel 2: V transpose (fp16 -> fp16):  g_vt[b][h][s] = g_v16[b][s][h]
// =====================================================================
__global__ void __launch_bounds__(256) transpose_v()
{
    __shared__ __half tile[32][40];   // 80 B rows: conflict-free both phases
    const int b  = blockIdx.z;
    const int s0 = blockIdx.x * 32;
    const int h0 = blockIdx.y * 32;
    const int tx = threadIdx.x, ty = threadIdx.y;
    const __half* src = g_v16 + ((size_t)b * S_LEN + s0) * HDIM + h0;
#pragma unroll
    for (int i = 0; i < 32; i += 8)
        tile[ty + i][tx] = src[(size_t)(ty + i) * HDIM + tx];
    __syncthreads();
    __half* dst = g_vt + ((size_t)b * HDIM + h0) * S_LEN + s0;
#pragma unroll
    for (int i = 0; i < 32; i += 8)
        dst[(size_t)(ty + i) * S_LEN + tx] = tile[tx][ty + i];
}

// =====================================================================
// Kernel 3: scores, single-pass.  P = (Q.K^T)/32 + beta*ssm (fp32).
// grid (16, 16, 4)
// =====================================================================
__global__ void __launch_bounds__(256, 2) scores_mma(
    const float* __restrict__ ssm, const float* __restrict__ beta_p)
{
    extern __shared__ char smem[];
    const int q0  = blockIdx.y * 128;
    const int kk0 = blockIdx.x * 128;
    const int b   = blockIdx.z;

    float acc[4][4][4];
    ACC_INIT(acc);
    gemm_h(g_q16 + (size_t)(b * S_LEN + q0) * HDIM,
           g_k16 + (size_t)(b * S_LEN + kk0) * HDIM,
           HDIM, HDIM, HDIM, smem, acc);

    const float beta = __ldg(beta_p);
    const int tid = threadIdx.x, wid = tid >> 5, lane = tid & 31;
    const int wm = (wid >> 2) * 64, wn = (wid & 3) * 32;
    const int g = lane >> 2, tig = lane & 3;
    float*       Pb = g_P + (size_t)b * S_LEN * S_LEN;
    const float* Sb = ssm + (size_t)b * S_LEN * S_LEN;
#pragma unroll
    for (int mt = 0; mt < 4; mt++)
#pragma unroll
        for (int nt = 0; nt < 4; nt++) {
            const int row = q0 + wm + mt * 16 + g;
            const int col = kk0 + wn + nt * 8 + tig * 2;
            const float2 s0 = *(const float2*)(Sb + (size_t)row * S_LEN + col);
            const float2 s1 = *(const float2*)(Sb + (size_t)(row + 8) * S_LEN + col);
            *(float2*)(Pb + (size_t)row * S_LEN + col) =
                make_float2(acc[mt][nt][0] * SCALE_INV + beta * s0.x,
                            acc[mt][nt][1] * SCALE_INV + beta * s0.y);
            *(float2*)(Pb + (size_t)(row + 8) * S_LEN + col) =
                make_float2(acc[mt][nt][2] * SCALE_INV + beta * s1.x,
                            acc[mt][nt][3] * SCALE_INV + beta * s1.y);
        }
}

// =====================================================================
// Kernel 4: softmax (fp32 in) + fp16 probabilities out.
// =====================================================================
__global__ void __launch_bounds__(256) softmax_kernel()
{
    const int row = blockIdx.x;
    const float2* p = (const float2*)(g_P + (size_t)row * S_LEN);
    __half2* d = (__half2*)(g_p16 + (size_t)row * S_LEN);
    const int tid = threadIdx.x;

    float2 v[4];
    float mx = -1e30f;
#pragma unroll
    for (int i = 0; i < 4; i++) {
        v[i] = p[tid + (i << 8)];
        mx = fmaxf(mx, fmaxf(v[i].x, v[i].y));
    }
#pragma unroll
    for (int o = 16; o; o >>= 1) mx = fmaxf(mx, __shfl_xor_sync(0xffffffffu, mx, o));
    __shared__ float sred[8];
    if ((tid & 31) == 0) sred[tid >> 5] = mx;
    __syncthreads();
#pragma unroll
    for (int i = 0; i < 8; i++) mx = fmaxf(mx, sred[i]);

    float sum = 0.f;
#pragma unroll
    for (int i = 0; i < 4; i++) {
        v[i].x = __expf(v[i].x - mx); v[i].y = __expf(v[i].y - mx);
        sum += v[i].x + v[i].y;
    }
#pragma unroll
    for (int o = 16; o; o >>= 1) sum += __shfl_xor_sync(0xffffffffu, sum, o);
    __syncthreads();
    if ((tid & 31) == 0) sred[tid >> 5] = sum;
    __syncthreads();
    sum = 0.f;
#pragma unroll
    for (int i = 0; i < 8; i++) sum += sred[i];

    const float inv = 1.0f / sum;
#pragma unroll
    for (int i = 0; i < 4; i++)
        d[tid + (i << 8)] = __floats2half2_rn(v[i].x * inv, v[i].y * inv);
}

// =====================================================================
// Kernel 5: out = P.V, single-pass.  grid (8, 16, 4)
// =====================================================================
__global__ void __launch_bounds__(256, 2) out_mma(float* __restrict__ out)
{
    extern __shared__ char smem[];
    const int q0 = blockIdx.y * 128;
    const int h0 = blockIdx.x * 128;
    const int b  = blockIdx.z;

    float acc[4][4][4];
    ACC_INIT(acc);
    gemm_h(g_p16 + (size_t)(b * S_LEN + q0) * S_LEN,
           g_vt + (size_t)(b * HDIM + h0) * S_LEN,
           S_LEN, S_LEN, S_LEN, smem, acc);

    const int tid = threadIdx.x, wid = tid >> 5, lane = tid & 31;
    const int wm = (wid >> 2) * 64, wn = (wid & 3) * 32;
    const int g = lane >> 2, tig = lane & 3;
#pragma unroll
    for (int mt = 0; mt < 4; mt++)
#pragma unroll
        for (int nt = 0; nt < 4; nt++) {
            const int row = q0 + wm + mt * 16 + g;         // s (query)
            const int col = h0 + wn + nt * 8 + tig * 2;    // h
            float* d0 = out + (size_t)row * (BATCH * HDIM) + (size_t)b * HDIM + col;
            float* d1 = out + (size_t)(row + 8) * (BATCH * HDIM) + (size_t)b * HDIM + col;
            *(float2*)d0 = make_float2(acc[mt][nt][0], acc[mt][nt][1]);
            *(float2*)d1 = make_float2(acc[mt][nt][2], acc[mt][nt][3]);
        }
}

// =====================================================================
extern "C" void kernel_launch(void* const* d_in, const int* in_sizes, int n_in,
                              void* d_out, int out_size)
{
    const float* x    = (const float*)d_in[0];
    const float* ssm  = (const float*)d_in[1];
    const float* Wq   = (const float*)d_in[2];
    const float* bq   = (const float*)d_in[3];
    const float* Wk   = (const float*)d_in[4];
    const float* bk   = (const float*)d_in[5];
    const float* Wv   = (const float*)d_in[6];
    const float* bv   = (const float*)d_in[7];
    const float* beta = (const float*)d_in[8];
    float* out = (float*)d_out;

    cudaFuncSetAttribute(proj_mma,   cudaFuncAttributeMaxDynamicSharedMemorySize, SMEM1);
    cudaFuncSetAttribute(scores_mma, cudaFuncAttributeMaxDynamicSharedMemorySize, SMEM1);
    cudaFuncSetAttribute(out_mma,    cudaFuncAttributeMaxDynamicSharedMemorySize, SMEM1);

    dim3 blk(256);
    cvt_x<<<MROWS, blk>>>(x);
    cvt_w<<<dim3(HDIM, 3), blk>>>(Wq, Wk, Wv);

    proj_mma<<<dim3(HDIM / 128, MROWS / 128, 3), blk, SMEM1>>>(bq, bk, bv);

    transpose_v<<<dim3(S_LEN / 32, HDIM / 32, BATCH), dim3(32, 8)>>>();

    scores_mma<<<dim3(S_LEN / 128, S_LEN / 128, BATCH), blk, SMEM1>>>(ssm, beta);

    softmax_kernel<<<MROWS, blk>>>();

    out_mma<<<dim3(HDIM / 128, S_LEN / 128, BATCH), blk, SMEM1>>>(out);
}